// round 11
// baseline (speedup 1.0000x reference)
#include <cuda_runtime.h>
#include <cuda_bf16.h>
#include <math.h>
#include <stdint.h>
#include <mma.h>

using namespace nvcuda;

// ---------------- problem constants ----------------
#define TOKENS 4096      // B(4) * 32 * 32
#define EMB    768
#define NHEAD  12
#define HD     64
#define SEQ    1024      // tokens per image
#define BHEADS 48        // B * NHEAD
#define MLPD   3072
#define GRID32 32

typedef __nv_bfloat16 bf16;

// ---------------- scratch (device globals; no allocs allowed) ----------------
__device__ float g_h[TOKENS * EMB];
__device__ float g_relh[BHEADS * SEQ * GRID32];
__device__ float g_relw[BHEADS * SEQ * GRID32];

// activation hi/lo planes
__device__ bf16 g_colH[TOKENS * EMB],  g_colL[TOKENS * EMB];
__device__ bf16 g_xnH[TOKENS * EMB],   g_xnL[TOKENS * EMB];
__device__ bf16 g_qH[BHEADS * SEQ * HD], g_qL[BHEADS * SEQ * HD];
__device__ bf16 g_kH[BHEADS * SEQ * HD], g_kL[BHEADS * SEQ * HD];
__device__ bf16 g_vH[BHEADS * SEQ * HD], g_vL[BHEADS * SEQ * HD];
__device__ bf16 g_attnH[TOKENS * EMB], g_attnL[TOKENS * EMB];
__device__ bf16 g_mlpH[TOKENS * MLPD], g_mlpL[TOKENS * MLPD];

// weight hi/lo planes, [N,K] K-major
__device__ bf16 g_cwTH[EMB * EMB],              g_cwTL[EMB * EMB];
__device__ bf16 g_qkvTH[4 * 3 * EMB * EMB],     g_qkvTL[4 * 3 * EMB * EMB];
__device__ bf16 g_projTH[4 * EMB * EMB],        g_projTL[4 * EMB * EMB];
__device__ bf16 g_fc1TH[4 * MLPD * EMB],        g_fc1TL[4 * MLPD * EMB];
__device__ bf16 g_fc2TH[4 * EMB * MLPD],        g_fc2TL[4 * EMB * MLPD];

enum { EPI_CONVPOS = 1, EPI_QKV = 2, EPI_BIASRES = 5, EPI_GELU = 6 };

// ---------------- helpers ----------------
__device__ __forceinline__ void split1(float x, bf16& h, bf16& l)
{
    h = __float2bfloat16(x);
    l = __float2bfloat16(x - __bfloat162float(h));
}

__device__ __forceinline__ void split_store4(float4 v, bf16* ph, bf16* pl)
{
    bf16 h0, h1, h2, h3, l0, l1, l2, l3;
    split1(v.x, h0, l0); split1(v.y, h1, l1);
    split1(v.z, h2, l2); split1(v.w, h3, l3);
    __nv_bfloat162 a, b;
    a.x = h0; a.y = h1; b.x = h2; b.y = h3;
    reinterpret_cast<__nv_bfloat162*>(ph)[0] = a;
    reinterpret_cast<__nv_bfloat162*>(ph)[1] = b;
    a.x = l0; a.y = l1; b.x = l2; b.y = l3;
    reinterpret_cast<__nv_bfloat162*>(pl)[0] = a;
    reinterpret_cast<__nv_bfloat162*>(pl)[1] = b;
}

__device__ __forceinline__ uint32_t smem_u32(const void* p)
{
    return (uint32_t)__cvta_generic_to_shared(p);
}

__device__ __forceinline__ void cp16(uint32_t dst, const void* src)
{
    asm volatile("cp.async.cg.shared.global [%0], [%1], 16;\n" :: "r"(dst), "l"(src));
}
__device__ __forceinline__ void cp_commit()
{
    asm volatile("cp.async.commit_group;\n" ::: "memory");
}
template <int N>
__device__ __forceinline__ void cp_wait()
{
    asm volatile("cp.async.wait_group %0;\n" :: "n"(N) : "memory");
}

// stage NROWS x CFL bf16 from global (row stride ld halves) into smem (row stride ss halves)
template <int NROWS, int CFL, int THREADS>
__device__ __forceinline__ void ld_tile_h(const bf16* __restrict__ g, int ld,
                                          bf16* __restrict__ s, int ss, int tid)
{
    constexpr int CH = NROWS * (CFL / 8);      // 16-byte chunks
    static_assert(CH % THREADS == 0, "chunk mapping");
#pragma unroll
    for (int i = 0; i < CH / THREADS; i++) {
        int lin = i * THREADS + tid;
        int r = lin / (CFL / 8);
        int c = (lin - r * (CFL / 8)) * 8;
        cp16(smem_u32(s + r * ss + c), g + (size_t)r * ld + c);
    }
}

// ---------------- split-bf16 wmma GEMM with fused epilogues (projections) ----------------
template <int BM, int BN, int BK, int WM, int WN, int EPI, bool BROW>
__global__ __launch_bounds__((BM / WM) * (BN / WN) * 32)
void wgemm(const bf16* __restrict__ AH, const bf16* __restrict__ AL, int ldA,
           const bf16* __restrict__ BH, const bf16* __restrict__ BL, int ldB,
           float* __restrict__ C, int N, int K,
           size_t sAs, size_t sBs, size_t sCs,
           const float* __restrict__ bias,
           const float* __restrict__ aux1, const float* __restrict__ aux2,
           bf16* __restrict__ o0h, bf16* __restrict__ o0l,
           bf16* __restrict__ o1h, bf16* __restrict__ o1l,
           bf16* __restrict__ o2h, bf16* __restrict__ o2l,
           float scale)
{
    constexpr int WARPS_M = BM / WM;
    constexpr int WARPS_N = BN / WN;
    constexpr int THREADS = WARPS_M * WARPS_N * 32;
    constexpr int FM = WM / 16, FN = WN / 16;
    constexpr int SA = BK + 8;
    constexpr int SB = BROW ? (BN + 8) : (BK + 8);
    constexpr int BROWS = BROW ? BK : BN;
    constexpr int ASZ = BM * SA;
    constexpr int BSZ = BROWS * SB;
    constexpr int STAGE = 2 * (ASZ + BSZ);
    constexpr int SC = BN + 8;
    static_assert(BM * SC * 2 <= 2 * STAGE, "C staging fits");

    extern __shared__ bf16 smh[];

    const int z = blockIdx.z;
    AH += (size_t)z * sAs; AL += (size_t)z * sAs;
    BH += (size_t)z * sBs; BL += (size_t)z * sBs;
    if (C) C += (size_t)z * sCs;

    const int tid = threadIdx.x;
    const int wid = tid >> 5;
    const int warpM = wid % WARPS_M;
    const int warpN = wid / WARPS_M;
    const int row0 = blockIdx.y * BM;
    const int col0 = blockIdx.x * BN;

    wmma::fragment<wmma::accumulator, 16, 16, 16, float> acc[FM][FN];
#pragma unroll
    for (int i = 0; i < FM; i++)
#pragma unroll
        for (int j = 0; j < FN; j++) wmma::fill_fragment(acc[i][j], 0.f);

    const int KB = K / BK;

    auto stage_in = [&](int kb, int buf) {
        bf16* st = smh + buf * STAGE;
        ld_tile_h<BM, BK, THREADS>(AH + (size_t)row0 * ldA + kb * BK, ldA, st, SA, tid);
        ld_tile_h<BM, BK, THREADS>(AL + (size_t)row0 * ldA + kb * BK, ldA, st + ASZ, SA, tid);
        if constexpr (BROW) {
            ld_tile_h<BK, BN, THREADS>(BH + (size_t)kb * BK * ldB + col0, ldB, st + 2 * ASZ, SB, tid);
            ld_tile_h<BK, BN, THREADS>(BL + (size_t)kb * BK * ldB + col0, ldB, st + 2 * ASZ + BSZ, SB, tid);
        } else {
            ld_tile_h<BN, BK, THREADS>(BH + (size_t)col0 * ldB + kb * BK, ldB, st + 2 * ASZ, SB, tid);
            ld_tile_h<BN, BK, THREADS>(BL + (size_t)col0 * ldB + kb * BK, ldB, st + 2 * ASZ + BSZ, SB, tid);
        }
    };

    stage_in(0, 0);
    cp_commit();

    for (int kb = 0; kb < KB; kb++) {
        if (kb + 1 < KB) stage_in(kb + 1, (kb + 1) & 1);
        cp_commit();
        cp_wait<1>();
        __syncthreads();

        const bf16* st = smh + (kb & 1) * STAGE;
        const bf16* AHt = st;
        const bf16* ALt = st + ASZ;
        const bf16* BHt = st + 2 * ASZ;
        const bf16* BLt = st + 2 * ASZ + BSZ;

#pragma unroll
        for (int kk = 0; kk < BK / 16; kk++) {
            wmma::fragment<wmma::matrix_a, 16, 16, 16, bf16, wmma::row_major> ah[FM], al[FM];
#pragma unroll
            for (int i = 0; i < FM; i++) {
                wmma::load_matrix_sync(ah[i], AHt + (warpM * WM + i * 16) * SA + kk * 16, SA);
                wmma::load_matrix_sync(al[i], ALt + (warpM * WM + i * 16) * SA + kk * 16, SA);
            }
            if constexpr (BROW) {
                wmma::fragment<wmma::matrix_b, 16, 16, 16, bf16, wmma::row_major> bh[FN], bl[FN];
#pragma unroll
                for (int j = 0; j < FN; j++) {
                    wmma::load_matrix_sync(bh[j], BHt + kk * 16 * SB + warpN * WN + j * 16, SB);
                    wmma::load_matrix_sync(bl[j], BLt + kk * 16 * SB + warpN * WN + j * 16, SB);
                }
#pragma unroll
                for (int i = 0; i < FM; i++)
#pragma unroll
                    for (int j = 0; j < FN; j++) {
                        wmma::mma_sync(acc[i][j], ah[i], bh[j], acc[i][j]);
                        wmma::mma_sync(acc[i][j], ah[i], bl[j], acc[i][j]);
                        wmma::mma_sync(acc[i][j], al[i], bh[j], acc[i][j]);
                    }
            } else {
                wmma::fragment<wmma::matrix_b, 16, 16, 16, bf16, wmma::col_major> bh[FN], bl[FN];
#pragma unroll
                for (int j = 0; j < FN; j++) {
                    wmma::load_matrix_sync(bh[j], BHt + (warpN * WN + j * 16) * SB + kk * 16, SB);
                    wmma::load_matrix_sync(bl[j], BLt + (warpN * WN + j * 16) * SB + kk * 16, SB);
                }
#pragma unroll
                for (int i = 0; i < FM; i++)
#pragma unroll
                    for (int j = 0; j < FN; j++) {
                        wmma::mma_sync(acc[i][j], ah[i], bh[j], acc[i][j]);
                        wmma::mma_sync(acc[i][j], ah[i], bl[j], acc[i][j]);
                        wmma::mma_sync(acc[i][j], al[i], bh[j], acc[i][j]);
                    }
            }
        }
        __syncthreads();
    }

    float* smf = reinterpret_cast<float*>(smh);
#pragma unroll
    for (int i = 0; i < FM; i++)
#pragma unroll
        for (int j = 0; j < FN; j++)
            wmma::store_matrix_sync(smf + (size_t)(warpM * WM + i * 16) * SC + warpN * WN + j * 16,
                                    acc[i][j], SC, wmma::mem_row_major);
    __syncthreads();

    constexpr int QUADS = BM * BN / 4;
#pragma unroll 4
    for (int qd = tid; qd < QUADS; qd += THREADS) {
        const int r = qd / (BN / 4);
        const int c4 = (qd - r * (BN / 4)) * 4;
        const int m = row0 + r;
        const int n = col0 + c4;
        float4 v = *reinterpret_cast<const float4*>(smf + r * SC + c4);

        if constexpr (EPI == EPI_CONVPOS) {
            float4 bb = *reinterpret_cast<const float4*>(bias + n);
            float4 p = *reinterpret_cast<const float4*>(aux1 + (size_t)(m & (SEQ - 1)) * EMB + n);
            v.x += bb.x + p.x; v.y += bb.y + p.y; v.z += bb.z + p.z; v.w += bb.w + p.w;
            *reinterpret_cast<float4*>(C + (size_t)m * N + n) = v;
        } else if constexpr (EPI == EPI_QKV) {
            float4 bb = *reinterpret_cast<const float4*>(bias + n);
            v.x += bb.x; v.y += bb.y; v.z += bb.z; v.w += bb.w;
            const int which = n / EMB;
            const int rr = n - which * EMB;
            const int head = rr >> 6;
            const int d = rr & 63;
            const int b = m >> 10, nl = m & (SEQ - 1);
            bf16* dh = (which == 0) ? o0h : ((which == 1) ? o1h : o2h);
            bf16* dl = (which == 0) ? o0l : ((which == 1) ? o1l : o2l);
            size_t off = ((size_t)(b * NHEAD + head) * SEQ + nl) * HD + d;
            split_store4(v, dh + off, dl + off);
        } else if constexpr (EPI == EPI_BIASRES) {
            float4 bb = *reinterpret_cast<const float4*>(bias + n);
            float4 p = *reinterpret_cast<const float4*>(aux1 + (size_t)m * N + n);
            v.x += bb.x + p.x; v.y += bb.y + p.y; v.z += bb.z + p.z; v.w += bb.w + p.w;
            *reinterpret_cast<float4*>(C + (size_t)m * N + n) = v;
        } else if constexpr (EPI == EPI_GELU) {
            float4 bb = *reinterpret_cast<const float4*>(bias + n);
            v.x = 0.5f * (v.x + bb.x) * (1.f + erff((v.x + bb.x) * 0.70710678118654752f));
            v.y = 0.5f * (v.y + bb.y) * (1.f + erff((v.y + bb.y) * 0.70710678118654752f));
            v.z = 0.5f * (v.z + bb.z) * (1.f + erff((v.z + bb.z) * 0.70710678118654752f));
            v.w = 0.5f * (v.w + bb.w) * (1.f + erff((v.w + bb.w) * 0.70710678118654752f));
            split_store4(v, o0h + (size_t)m * N + n, o0l + (size_t)m * N + n);
        }
    }
}

constexpr int wg_smem_bytes(int BM, int BN, int BK, bool BROW)
{
    int ASZ = BM * (BK + 8);
    int BROWS = BROW ? BK : BN;
    int SB = BROW ? (BN + 8) : (BK + 8);
    int BSZ = BROWS * SB;
    return 2 * 2 * (ASZ + BSZ) * 2;
}

// ---------------- fused flash attention ----------------
// grid (SEQ/128, BHEADS), 256 threads. BQ=128 q rows, BKV=64 kv per iter, 16 iters.
// smem layout (bytes):
//   sq   @ 0       : 2 planes * 128*72 halves             = 36864
//   skv  @ 36864   : 2 stages * 4 planes * 64*72 halves   = 73728
//   Ss   @ 110592  : 128*72 floats (S tile / P-hi halves) = 36864
//   Plo  @ 147456  : 128*72 halves (P-lo plane)           = 18432
//   Os   @ 165888  : 128*72 floats (O accumulator)        = 36864
//   m,l  @ 202752  : 2 * 128 floats                       = 1024
#define FA_SMEM 203776
#define FA_ITERS (SEQ / 64)

__global__ __launch_bounds__(256)
void flash_kernel(const bf16* __restrict__ qH, const bf16* __restrict__ qL,
                  const bf16* __restrict__ kH, const bf16* __restrict__ kL,
                  const bf16* __restrict__ vH, const bf16* __restrict__ vL,
                  const float* __restrict__ relh, const float* __restrict__ relw,
                  bf16* __restrict__ attnH, bf16* __restrict__ attnL, float scale)
{
    extern __shared__ char fsm[];
    bf16*  sq   = (bf16*)fsm;                    // qH plane; qL at +9216 halves
    bf16*  skv  = (bf16*)(fsm + 36864);          // stage s: 4 planes of 4608 halves
    float* Ss   = (float*)(fsm + 110592);
    bf16*  sPlo = (bf16*)(fsm + 147456);
    float* Os   = (float*)(fsm + 165888);
    float* ms   = (float*)(fsm + 202752);
    float* ls   = ms + 128;

    const int tid = threadIdx.x;
    const int wid = tid >> 5;
    const int bh = blockIdx.y;
    const int q0 = blockIdx.x * 128;
    const size_t qgbase = ((size_t)bh * SEQ + q0) * HD;

    // q planes: 128 rows x 64 halves each, 1024 chunks/plane
#pragma unroll
    for (int i = 0; i < 4; i++) {
        int lin = i * 256 + tid;
        int r = lin >> 3, c = (lin & 7) * 8;
        cp16(smem_u32(sq + r * 72 + c),        qH + qgbase + r * HD + c);
        cp16(smem_u32(sq + 9216 + r * 72 + c), qL + qgbase + r * HD + c);
    }

    auto load_kv = [&](int kt) {
        const size_t kb = ((size_t)bh * SEQ + kt * 64) * HD;
        bf16* dst = skv + (kt & 1) * 18432;
        const bf16* s0 = kH + kb;
        const bf16* s1 = kL + kb;
        const bf16* s2 = vH + kb;
        const bf16* s3 = vL + kb;
#pragma unroll
        for (int i = 0; i < 8; i++) {
            int lin = i * 256 + tid;       // 0..2047
            int pl = lin >> 9;
            int rr = (lin >> 3) & 63;
            int cc = (lin & 7) * 8;
            const bf16* src = (pl == 0) ? s0 : ((pl == 1) ? s1 : ((pl == 2) ? s2 : s3));
            cp16(smem_u32(dst + pl * 4608 + rr * 72 + cc), src + (size_t)rr * HD + cc);
        }
    };

    load_kv(0);
    cp_commit();                                   // group: q + kv(0)

    // init O, m, l
#pragma unroll
    for (int i = 0; i < 32; i++) {
        int lin = i * 256 + tid;                   // 0..8191
        int r = lin >> 6, c = lin & 63;
        Os[r * 72 + c] = 0.f;
    }
    if (tid < 128) { ms[tid] = -1e30f; ls[tid] = 0.f; }

    const int wM = wid >> 1;                       // 0..3
    const int wN = wid & 1;                        // 0..1
    const int srow = tid >> 1;                     // softmax row
    const int shh = tid & 1;                       // softmax half
    const float* rhrow = relh + ((size_t)bh * SEQ + q0 + srow) * GRID32;
    const float* rwrow = relw + ((size_t)bh * SEQ + q0 + srow) * GRID32;

    for (int kt = 0; kt < FA_ITERS; kt++) {
        if (kt + 1 < FA_ITERS) { load_kv(kt + 1); cp_commit(); cp_wait<1>(); }
        else                   { cp_wait<0>(); }
        __syncthreads();

        const bf16* kb_hi = skv + (kt & 1) * 18432;
        const bf16* kb_lo = kb_hi + 4608;
        const bf16* vb_hi = kb_hi + 2 * 4608;
        const bf16* vb_lo = kb_hi + 3 * 4608;

        // ---- S = q @ k^T (split 3-MMA), tile 128x64, warps 4x2 of 32x32 ----
        {
            wmma::fragment<wmma::accumulator, 16, 16, 16, float> acc[2][2];
#pragma unroll
            for (int i = 0; i < 2; i++)
#pragma unroll
                for (int j = 0; j < 2; j++) wmma::fill_fragment(acc[i][j], 0.f);
#pragma unroll
            for (int kk = 0; kk < 4; kk++) {
                wmma::fragment<wmma::matrix_a, 16, 16, 16, bf16, wmma::row_major> ah[2], al[2];
                wmma::fragment<wmma::matrix_b, 16, 16, 16, bf16, wmma::col_major> bh[2], bl[2];
#pragma unroll
                for (int i = 0; i < 2; i++) {
                    wmma::load_matrix_sync(ah[i], sq + (wM * 32 + i * 16) * 72 + kk * 16, 72);
                    wmma::load_matrix_sync(al[i], sq + 9216 + (wM * 32 + i * 16) * 72 + kk * 16, 72);
                }
#pragma unroll
                for (int j = 0; j < 2; j++) {
                    wmma::load_matrix_sync(bh[j], kb_hi + (wN * 32 + j * 16) * 72 + kk * 16, 72);
                    wmma::load_matrix_sync(bl[j], kb_lo + (wN * 32 + j * 16) * 72 + kk * 16, 72);
                }
#pragma unroll
                for (int i = 0; i < 2; i++)
#pragma unroll
                    for (int j = 0; j < 2; j++) {
                        wmma::mma_sync(acc[i][j], ah[i], bh[j], acc[i][j]);
                        wmma::mma_sync(acc[i][j], ah[i], bl[j], acc[i][j]);
                        wmma::mma_sync(acc[i][j], al[i], bh[j], acc[i][j]);
                    }
            }
#pragma unroll
            for (int i = 0; i < 2; i++)
#pragma unroll
                for (int j = 0; j < 2; j++)
                    wmma::store_matrix_sync(Ss + (wM * 32 + i * 16) * 72 + wN * 32 + j * 16,
                                            acc[i][j], 72, wmma::mem_row_major);
        }
        __syncthreads();

        // ---- online softmax (2 threads per row; cols shh*32..+32) ----
        {
            float* Srow = Ss + srow * 72;
            const int c0 = shh * 32;
            const float rh0 = rhrow[kt * 2];
            const float rh1 = rhrow[kt * 2 + 1];
            float mx = -1e30f;
#pragma unroll 8
            for (int c = c0; c < c0 + 32; c++) {
                float t = Srow[c] * scale + ((c >> 5) ? rh1 : rh0) + rwrow[c & 31];
                Srow[c] = t;
                mx = fmaxf(mx, t);
            }
            mx = fmaxf(mx, __shfl_xor_sync(0xffffffffu, mx, 1));
            const float mo = ms[srow];
            const float mn = fmaxf(mo, mx);
            const float alpha = __expf(mo - mn);

            bf16* hi = reinterpret_cast<bf16*>(Srow);   // cols<32 -> half c; cols>=32 -> half 32+c
            bf16* lo = sPlo + srow * 72;
            float psum = 0.f;
#pragma unroll 8
            for (int c = c0; c < c0 + 32; c++) {
                float p = __expf(Srow[c] - mn);
                psum += p;
                bf16 h = __float2bfloat16(p);
                hi[(c < 32) ? c : 32 + c] = h;
                lo[c] = __float2bfloat16(p - __bfloat162float(h));
            }
            psum += __shfl_xor_sync(0xffffffffu, psum, 1);
            if (shh == 0) { ms[srow] = mn; ls[srow] = ls[srow] * alpha + psum; }
            float* Orow = Os + srow * 72;
#pragma unroll 8
            for (int c = c0; c < c0 + 32; c++) Orow[c] *= alpha;
        }
        __syncthreads();

        // ---- O += P @ V (split 3-MMA), O 128x64, warps 4x2 of 32x32, K=64 ----
        {
            const bf16* Ph = reinterpret_cast<const bf16*>(Ss);   // row stride 144 halves
            wmma::fragment<wmma::accumulator, 16, 16, 16, float> acc[2][2];
#pragma unroll
            for (int i = 0; i < 2; i++)
#pragma unroll
                for (int j = 0; j < 2; j++)
                    wmma::load_matrix_sync(acc[i][j],
                        Os + (wM * 32 + i * 16) * 72 + wN * 32 + j * 16, 72, wmma::mem_row_major);
#pragma unroll
            for (int kk = 0; kk < 4; kk++) {
                const int hoff = kk * 16 + ((kk >= 2) ? 32 : 0);
                wmma::fragment<wmma::matrix_a, 16, 16, 16, bf16, wmma::row_major> ah[2], al[2];
                wmma::fragment<wmma::matrix_b, 16, 16, 16, bf16, wmma::row_major> bh[2], bl[2];
#pragma unroll
                for (int i = 0; i < 2; i++) {
                    wmma::load_matrix_sync(ah[i], Ph + (wM * 32 + i * 16) * 144 + hoff, 144);
                    wmma::load_matrix_sync(al[i], sPlo + (wM * 32 + i * 16) * 72 + kk * 16, 72);
                }
#pragma unroll
                for (int j = 0; j < 2; j++) {
                    wmma::load_matrix_sync(bh[j], vb_hi + (kk * 16) * 72 + wN * 32 + j * 16, 72);
                    wmma::load_matrix_sync(bl[j], vb_lo + (kk * 16) * 72 + wN * 32 + j * 16, 72);
                }
#pragma unroll
                for (int i = 0; i < 2; i++)
#pragma unroll
                    for (int j = 0; j < 2; j++) {
                        wmma::mma_sync(acc[i][j], ah[i], bh[j], acc[i][j]);
                        wmma::mma_sync(acc[i][j], ah[i], bl[j], acc[i][j]);
                        wmma::mma_sync(acc[i][j], al[i], bh[j], acc[i][j]);
                    }
            }
#pragma unroll
            for (int i = 0; i < 2; i++)
#pragma unroll
                for (int j = 0; j < 2; j++)
                    wmma::store_matrix_sync(Os + (wM * 32 + i * 16) * 72 + wN * 32 + j * 16,
                                            acc[i][j], 72, wmma::mem_row_major);
        }
        __syncthreads();
    }

    // ---- epilogue: O /= l, split-store to attn planes ----
    {
        const int b = bh / NHEAD;
        const int head = bh - b * NHEAD;
#pragma unroll
        for (int i = 0; i < 8; i++) {
            int lin = i * 256 + tid;               // 0..2047 quads
            int r = lin >> 4, c4 = (lin & 15) * 4;
            float inv = 1.f / ls[r];
            const float* Orow = Os + r * 72;
            float4 v;
            v.x = Orow[c4 + 0] * inv; v.y = Orow[c4 + 1] * inv;
            v.z = Orow[c4 + 2] * inv; v.w = Orow[c4 + 3] * inv;
            size_t off = ((size_t)(b * SEQ + q0 + r)) * EMB + head * HD + c4;
            split_store4(v, attnH + off, attnL + off);
        }
    }
}

// ---------------- weight prep: split(+transpose) fp32 -> bf16 hi/lo [N,K] ----------------
struct PrepJob {
    const float* src;
    bf16* dh;
    bf16* dl;
    int K;
    int N;
    int trans;
};
struct Jobs8 { PrepJob j[8]; };

__global__ __launch_bounds__(256)
void prep_kernel(Jobs8 jobs)
{
    const PrepJob jb = jobs.j[blockIdx.z];
    __shared__ float t[32][33];
    const int x = threadIdx.x, y = threadIdx.y;
    if (jb.trans) {
        const int n0 = blockIdx.x * 32, k0 = blockIdx.y * 32;
        if (n0 >= jb.N || k0 >= jb.K) return;
#pragma unroll
        for (int i = y; i < 32; i += 8) t[i][x] = jb.src[(size_t)(k0 + i) * jb.N + n0 + x];
        __syncthreads();
#pragma unroll
        for (int i = y; i < 32; i += 8) {
            bf16 h, l;
            split1(t[x][i], h, l);
            size_t o = (size_t)(n0 + i) * jb.K + k0 + x;
            jb.dh[o] = h; jb.dl[o] = l;
        }
    } else {
        const int k0 = blockIdx.x * 32, n0 = blockIdx.y * 32;
        if (k0 >= jb.K || n0 >= jb.N) return;
#pragma unroll
        for (int i = y; i < 32; i += 8) {
            size_t o = (size_t)(n0 + i) * jb.K + k0 + x;
            bf16 h, l;
            split1(jb.src[o], h, l);
            jb.dh[o] = h; jb.dl[o] = l;
        }
    }
}

// ---------------- im2col (split output) ----------------
__global__ void im2col_kernel(const float* __restrict__ x,
                              bf16* __restrict__ colH, bf16* __restrict__ colL)
{
    int idx = blockIdx.x * blockDim.x + threadIdx.x;
    if (idx >= TOKENS * EMB) return;
    int m = idx / EMB, kk = idx - m * EMB;
    int b = m >> 10, p = m & 1023, ph = p >> 5, pw = p & 31;
    int c = kk >> 8, r = kk & 255, kh = r >> 4, kw = r & 15;
    float v = x[((size_t)(b * 3 + c) * 512 + (ph * 16 + kh)) * 512 + pw * 16 + kw];
    bf16 h, l;
    split1(v, h, l);
    colH[idx] = h; colL[idx] = l;
}

// ---------------- layernorm (split output planes) ----------------
__device__ __forceinline__ float warpReduceSum(float v)
{
#pragma unroll
    for (int o = 16; o; o >>= 1) v += __shfl_xor_sync(0xffffffffu, v, o);
    return v;
}

__global__ __launch_bounds__(256)
void ln_kernel(const float* __restrict__ in, const float* __restrict__ w,
               const float* __restrict__ b,
               bf16* __restrict__ outH, bf16* __restrict__ outL)
{
    __shared__ float sh[8];
    const int row = blockIdx.x;
    const int t = threadIdx.x;
    const float* x = in + (size_t)row * EMB;
    float v0 = x[t], v1 = x[t + 256], v2 = x[t + 512];
    float s = warpReduceSum(v0 + v1 + v2);
    if ((t & 31) == 0) sh[t >> 5] = s;
    __syncthreads();
    float mean = (sh[0] + sh[1] + sh[2] + sh[3] + sh[4] + sh[5] + sh[6] + sh[7]) * (1.f / EMB);
    float d0 = v0 - mean, d1 = v1 - mean, d2 = v2 - mean;
    __syncthreads();
    float s2 = warpReduceSum(d0 * d0 + d1 * d1 + d2 * d2);
    if ((t & 31) == 0) sh[t >> 5] = s2;
    __syncthreads();
    float var = (sh[0] + sh[1] + sh[2] + sh[3] + sh[4] + sh[5] + sh[6] + sh[7]) * (1.f / EMB);
    float rstd = rsqrtf(var + 1e-5f);
    bf16 h, l;
    size_t base = (size_t)row * EMB;
    float o0 = d0 * rstd * w[t] + b[t];
    float o1 = d1 * rstd * w[t + 256] + b[t + 256];
    float o2 = d2 * rstd * w[t + 512] + b[t + 512];
    split1(o0, h, l); outH[base + t] = h;       outL[base + t] = l;
    split1(o1, h, l); outH[base + t + 256] = h; outL[base + t + 256] = l;
    split1(o2, h, l); outH[base + t + 512] = h; outL[base + t + 512] = l;
}

// ---------------- decomposed rel-pos dot products ----------------
__global__ __launch_bounds__(64)
void rel_kernel(const bf16* __restrict__ qH, const bf16* __restrict__ qL,
                const float* __restrict__ rph, const float* __restrict__ rpw,
                float* __restrict__ relh, float* __restrict__ relw)
{
    const int bq = blockIdx.x;
    const int p = bq & (SEQ - 1);
    const int qh = p >> 5, qw = p & 31;
    __shared__ float qs[HD];
    const int t = threadIdx.x;
    qs[t] = __bfloat162float(qH[(size_t)bq * HD + t]) + __bfloat162float(qL[(size_t)bq * HD + t]);
    __syncthreads();
    const int kidx = t & 31;
    const float* tab = (t < 32) ? (rph + (qh - kidx + 31) * HD)
                                : (rpw + (qw - kidx + 31) * HD);
    float s = 0.f;
#pragma unroll
    for (int d = 0; d < HD; d++) s = fmaf(qs[d], tab[d], s);
    if (t < 32) relh[(size_t)bq * GRID32 + kidx] = s;
    else        relw[(size_t)bq * GRID32 + kidx] = s;
}

// ---------------- host orchestration ----------------
extern "C" void kernel_launch(void* const* d_in, const int* in_sizes, int n_in,
                              void* d_out, int out_size)
{
    const float* x      = (const float*)d_in[0];
    const float* conv_w = (const float*)d_in[1];
    const float* conv_b = (const float*)d_in[2];
    const float* pos    = (const float*)d_in[3];
    const float* ln1_w  = (const float*)d_in[4];
    const float* ln1_b  = (const float*)d_in[5];
    const float* qkv_w  = (const float*)d_in[6];
    const float* qkv_b  = (const float*)d_in[7];
    const float* proj_w = (const float*)d_in[8];
    const float* proj_b = (const float*)d_in[9];
    const float* rph    = (const float*)d_in[10];
    const float* rpw    = (const float*)d_in[11];
    const float* ln2_w  = (const float*)d_in[12];
    const float* ln2_b  = (const float*)d_in[13];
    const float* fc1_w  = (const float*)d_in[14];
    const float* fc1_b  = (const float*)d_in[15];
    const float* fc2_w  = (const float*)d_in[16];
    const float* fc2_b  = (const float*)d_in[17];

    float *h, *relh, *relw;
    bf16 *colH, *colL, *xnH, *xnL, *qH, *qL, *kH, *kL, *vH, *vL, *attnH, *attnL, *mlpH, *mlpL;
    bf16 *cwTH, *cwTL, *qkvTH, *qkvTL, *projTH, *projTL, *fc1TH, *fc1TL, *fc2TH, *fc2TL;
    cudaGetSymbolAddress((void**)&h, g_h);
    cudaGetSymbolAddress((void**)&relh, g_relh);
    cudaGetSymbolAddress((void**)&relw, g_relw);
    cudaGetSymbolAddress((void**)&colH, g_colH);   cudaGetSymbolAddress((void**)&colL, g_colL);
    cudaGetSymbolAddress((void**)&xnH, g_xnH);     cudaGetSymbolAddress((void**)&xnL, g_xnL);
    cudaGetSymbolAddress((void**)&qH, g_qH);       cudaGetSymbolAddress((void**)&qL, g_qL);
    cudaGetSymbolAddress((void**)&kH, g_kH);       cudaGetSymbolAddress((void**)&kL, g_kL);
    cudaGetSymbolAddress((void**)&vH, g_vH);       cudaGetSymbolAddress((void**)&vL, g_vL);
    cudaGetSymbolAddress((void**)&attnH, g_attnH); cudaGetSymbolAddress((void**)&attnL, g_attnL);
    cudaGetSymbolAddress((void**)&mlpH, g_mlpH);   cudaGetSymbolAddress((void**)&mlpL, g_mlpL);
    cudaGetSymbolAddress((void**)&cwTH, g_cwTH);   cudaGetSymbolAddress((void**)&cwTL, g_cwTL);
    cudaGetSymbolAddress((void**)&qkvTH, g_qkvTH); cudaGetSymbolAddress((void**)&qkvTL, g_qkvTL);
    cudaGetSymbolAddress((void**)&projTH, g_projTH); cudaGetSymbolAddress((void**)&projTL, g_projTL);
    cudaGetSymbolAddress((void**)&fc1TH, g_fc1TH); cudaGetSymbolAddress((void**)&fc1TL, g_fc1TL);
    cudaGetSymbolAddress((void**)&fc2TH, g_fc2TH); cudaGetSymbolAddress((void**)&fc2TL, g_fc2TL);

    constexpr int SM_BIG = wg_smem_bytes(128, 128, 64, false);

    cudaFuncSetAttribute((const void*)wgemm<128,128,64,64,32,EPI_CONVPOS,false>,
                         cudaFuncAttributeMaxDynamicSharedMemorySize, SM_BIG);
    cudaFuncSetAttribute((const void*)wgemm<128,128,64,64,32,EPI_QKV,false>,
                         cudaFuncAttributeMaxDynamicSharedMemorySize, SM_BIG);
    cudaFuncSetAttribute((const void*)wgemm<128,128,64,64,32,EPI_BIASRES,false>,
                         cudaFuncAttributeMaxDynamicSharedMemorySize, SM_BIG);
    cudaFuncSetAttribute((const void*)wgemm<128,128,64,64,32,EPI_GELU,false>,
                         cudaFuncAttributeMaxDynamicSharedMemorySize, SM_BIG);
    cudaFuncSetAttribute((const void*)flash_kernel,
                         cudaFuncAttributeMaxDynamicSharedMemorySize, FA_SMEM);

    const float scale = 0.125f;  // HD^-0.5
    const dim3 tb(32, 8);

    // ---- weight prep ----
    {
        Jobs8 J{};
        for (int l = 0; l < 4; l++) {
            J.j[l]     = { qkv_w  + (size_t)l * EMB * 3 * EMB,
                           qkvTH  + (size_t)l * 3 * EMB * EMB,
                           qkvTL  + (size_t)l * 3 * EMB * EMB, EMB, 3 * EMB, 1 };
            J.j[4 + l] = { proj_w + (size_t)l * EMB * EMB,
                           projTH + (size_t)l * EMB * EMB,
                           projTL + (size_t)l * EMB * EMB, EMB, EMB, 1 };
        }
        prep_kernel<<<dim3(3 * EMB / 32, EMB / 32, 8), tb>>>(J);
    }
    {
        Jobs8 J{};
        for (int l = 0; l < 4; l++)
            J.j[l] = { fc1_w + (size_t)l * EMB * MLPD,
                       fc1TH + (size_t)l * MLPD * EMB,
                       fc1TL + (size_t)l * MLPD * EMB, EMB, MLPD, 1 };
        prep_kernel<<<dim3(MLPD / 32, EMB / 32, 4), tb>>>(J);
    }
    {
        Jobs8 J{};
        for (int l = 0; l < 4; l++)
            J.j[l] = { fc2_w + (size_t)l * MLPD * EMB,
                       fc2TH + (size_t)l * EMB * MLPD,
                       fc2TL + (size_t)l * EMB * MLPD, MLPD, EMB, 1 };
        prep_kernel<<<dim3(EMB / 32, MLPD / 32, 4), tb>>>(J);
    }
    {
        Jobs8 J{};
        J.j[0] = { conv_w, cwTH, cwTL, EMB, EMB, 0 };
        prep_kernel<<<dim3(EMB / 32, EMB / 32, 1), tb>>>(J);
    }

    im2col_kernel<<<(TOKENS * EMB + 255) / 256, 256>>>(x, colH, colL);

    wgemm<128,128,64,64,32,EPI_CONVPOS,false><<<dim3(EMB/128, TOKENS/128), 256, SM_BIG>>>(
        colH, colL, EMB, cwTH, cwTL, EMB, h, EMB, EMB, 0, 0, 0,
        conv_b, pos, nullptr, nullptr, nullptr, nullptr, nullptr, nullptr, nullptr, 0.f);

    for (int i = 0; i < 4; i++) {
        ln_kernel<<<TOKENS, 256>>>(h, ln1_w + i * EMB, ln1_b + i * EMB, xnH, xnL);

        wgemm<128,128,64,64,32,EPI_QKV,false><<<dim3(3*EMB/128, TOKENS/128), 256, SM_BIG>>>(
            xnH, xnL, EMB,
            qkvTH + (size_t)i * 3 * EMB * EMB, qkvTL + (size_t)i * 3 * EMB * EMB, EMB,
            nullptr, 3 * EMB, EMB, 0, 0, 0,
            qkv_b + (size_t)i * 3 * EMB, nullptr, nullptr,
            qH, qL, kH, kL, vH, vL, 0.f);

        rel_kernel<<<BHEADS * SEQ, 64>>>(qH, qL,
                                         rph + (size_t)i * 63 * HD, rpw + (size_t)i * 63 * HD,
                                         relh, relw);

        // fused attention: S + rel bias + softmax + P@V, no global S
        flash_kernel<<<dim3(SEQ / 128, BHEADS), 256, FA_SMEM>>>(
            qH, qL, kH, kL, vH, vL, relh, relw, attnH, attnL, scale);

        wgemm<128,128,64,64,32,EPI_BIASRES,false><<<dim3(EMB/128, TOKENS/128), 256, SM_BIG>>>(
            attnH, attnL, EMB,
            projTH + (size_t)i * EMB * EMB, projTL + (size_t)i * EMB * EMB, EMB,
            h, EMB, EMB, 0, 0, 0,
            proj_b + (size_t)i * EMB, h, nullptr,
            nullptr, nullptr, nullptr, nullptr, nullptr, nullptr, 0.f);

        ln_kernel<<<TOKENS, 256>>>(h, ln2_w + i * EMB, ln2_b + i * EMB, xnH, xnL);

        wgemm<128,128,64,64,32,EPI_GELU,false><<<dim3(MLPD/128, TOKENS/128), 256, SM_BIG>>>(
            xnH, xnL, EMB,
            fc1TH + (size_t)i * MLPD * EMB, fc1TL + (size_t)i * MLPD * EMB, EMB,
            nullptr, MLPD, EMB, 0, 0, 0,
            fc1_b + (size_t)i * MLPD, nullptr, nullptr,
            mlpH, mlpL, nullptr, nullptr, nullptr, nullptr, 0.f);

        float* dst = (i == 3) ? (float*)d_out : h;
        wgemm<128,128,64,64,32,EPI_BIASRES,false><<<dim3(EMB/128, TOKENS/128), 256, SM_BIG>>>(
            mlpH, mlpL, MLPD,
            fc2TH + (size_t)i * EMB * MLPD, fc2TL + (size_t)i * EMB * MLPD, MLPD,
            dst, EMB, MLPD, 0, 0, 0,
            fc2_b + (size_t)i * EMB, h, nullptr,
            nullptr, nullptr, nullptr, nullptr, nullptr, nullptr, 0.f);
    }
}

// round 13
// speedup vs baseline: 1.1207x; 1.1207x over previous
#include <cuda_runtime.h>
#include <cuda_bf16.h>
#include <math.h>
#include <stdint.h>
#include <mma.h>

using namespace nvcuda;

// ---------------- problem constants ----------------
#define TOKENS 4096      // B(4) * 32 * 32
#define EMB    768
#define NHEAD  12
#define HD     64
#define SEQ    1024      // tokens per image
#define BHEADS 48        // B * NHEAD
#define MLPD   3072
#define GRID32 32

typedef __nv_bfloat16 bf16;

// ---------------- scratch (device globals; no allocs allowed) ----------------
__device__ float g_h[TOKENS * EMB];
__device__ float g_relh[BHEADS * SEQ * GRID32];
__device__ float g_relw[BHEADS * SEQ * GRID32];
__device__ float g_S[(size_t)BHEADS * SEQ * SEQ];   // fp32 logits; softmax rewrites rows as bf16 hi/lo planes

// activation hi/lo planes
__device__ bf16 g_colH[TOKENS * EMB],  g_colL[TOKENS * EMB];
__device__ bf16 g_xnH[TOKENS * EMB],   g_xnL[TOKENS * EMB];
__device__ bf16 g_qH[BHEADS * SEQ * HD], g_qL[BHEADS * SEQ * HD];
__device__ bf16 g_kH[BHEADS * SEQ * HD], g_kL[BHEADS * SEQ * HD];
__device__ bf16 g_vH[BHEADS * SEQ * HD], g_vL[BHEADS * SEQ * HD];
__device__ bf16 g_attnH[TOKENS * EMB], g_attnL[TOKENS * EMB];
__device__ bf16 g_mlpH[TOKENS * MLPD], g_mlpL[TOKENS * MLPD];

// weight hi/lo planes, [N,K] K-major
__device__ bf16 g_cwTH[EMB * EMB],              g_cwTL[EMB * EMB];
__device__ bf16 g_qkvTH[4 * 3 * EMB * EMB],     g_qkvTL[4 * 3 * EMB * EMB];
__device__ bf16 g_projTH[4 * EMB * EMB],        g_projTL[4 * EMB * EMB];
__device__ bf16 g_fc1TH[4 * MLPD * EMB],        g_fc1TL[4 * MLPD * EMB];
__device__ bf16 g_fc2TH[4 * EMB * MLPD],        g_fc2TL[4 * EMB * MLPD];

enum { EPI_CONVPOS = 1, EPI_QKV = 2, EPI_SREL = 3, EPI_AV = 4, EPI_BIASRES = 5, EPI_GELU = 6 };

// ---------------- helpers ----------------
__device__ __forceinline__ void split1(float x, bf16& h, bf16& l)
{
    h = __float2bfloat16(x);
    l = __float2bfloat16(x - __bfloat162float(h));
}

__device__ __forceinline__ void split_store4(float4 v, bf16* ph, bf16* pl)
{
    bf16 h0, h1, h2, h3, l0, l1, l2, l3;
    split1(v.x, h0, l0); split1(v.y, h1, l1);
    split1(v.z, h2, l2); split1(v.w, h3, l3);
    __nv_bfloat162 a, b;
    a.x = h0; a.y = h1; b.x = h2; b.y = h3;
    reinterpret_cast<__nv_bfloat162*>(ph)[0] = a;
    reinterpret_cast<__nv_bfloat162*>(ph)[1] = b;
    a.x = l0; a.y = l1; b.x = l2; b.y = l3;
    reinterpret_cast<__nv_bfloat162*>(pl)[0] = a;
    reinterpret_cast<__nv_bfloat162*>(pl)[1] = b;
}

__device__ __forceinline__ uint32_t smem_u32(const void* p)
{
    return (uint32_t)__cvta_generic_to_shared(p);
}

__device__ __forceinline__ void cp16(uint32_t dst, const void* src)
{
    asm volatile("cp.async.cg.shared.global [%0], [%1], 16;\n" :: "r"(dst), "l"(src));
}
__device__ __forceinline__ void cp_commit()
{
    asm volatile("cp.async.commit_group;\n" ::: "memory");
}
template <int N>
__device__ __forceinline__ void cp_wait()
{
    asm volatile("cp.async.wait_group %0;\n" :: "n"(N) : "memory");
}

// stage NROWS x CFL bf16 from global (row stride ld halves) into smem (row stride ss halves)
template <int NROWS, int CFL, int THREADS>
__device__ __forceinline__ void ld_tile_h(const bf16* __restrict__ g, int ld,
                                          bf16* __restrict__ s, int ss, int tid)
{
    constexpr int CH = NROWS * (CFL / 8);      // 16-byte chunks
    static_assert(CH % THREADS == 0, "chunk mapping");
#pragma unroll
    for (int i = 0; i < CH / THREADS; i++) {
        int lin = i * THREADS + tid;
        int r = lin / (CFL / 8);
        int c = (lin - r * (CFL / 8)) * 8;
        cp16(smem_u32(s + r * ss + c), g + (size_t)r * ld + c);
    }
}

// ---------------- split-bf16 wmma GEMM with fused epilogues ----------------
// C = (AH+AL) @ (BH+BL)^T', dropping AL*BL. A: [M,K] row-major planes.
// BROW=false: B planes are [N,K] row-major (wmma col_major). BROW=true: [K,N] row-major.
// 2 CTAs/SM target: BK=32 stages (<=82KB smem), __launch_bounds__(threads, 2).
template <int BM, int BN, int BK, int WM, int WN, int EPI, bool BROW>
__global__ __launch_bounds__((BM / WM) * (BN / WN) * 32, 2)
void wgemm(const bf16* __restrict__ AH, const bf16* __restrict__ AL, int ldA,
           const bf16* __restrict__ BH, const bf16* __restrict__ BL, int ldB,
           float* __restrict__ C, int N, int K,
           size_t sAs, size_t sBs, size_t sCs,
           const float* __restrict__ bias,
           const float* __restrict__ aux1, const float* __restrict__ aux2,
           bf16* __restrict__ o0h, bf16* __restrict__ o0l,
           bf16* __restrict__ o1h, bf16* __restrict__ o1l,
           bf16* __restrict__ o2h, bf16* __restrict__ o2l,
           float scale)
{
    constexpr int WARPS_M = BM / WM;
    constexpr int WARPS_N = BN / WN;
    constexpr int THREADS = WARPS_M * WARPS_N * 32;
    constexpr int FM = WM / 16, FN = WN / 16;
    constexpr int SA = BK + 8;
    constexpr int SB = BROW ? (BN + 8) : (BK + 8);
    constexpr int BROWS = BROW ? BK : BN;
    constexpr int ASZ = BM * SA;
    constexpr int BSZ = BROWS * SB;
    constexpr int STAGE = 2 * (ASZ + BSZ);
    constexpr int SC = BN + 8;
    static_assert(BM * SC * 2 <= 2 * STAGE, "C staging fits");

    extern __shared__ bf16 smh[];

    const int z = blockIdx.z;
    AH += (size_t)z * sAs; AL += (size_t)z * sAs;
    BH += (size_t)z * sBs; BL += (size_t)z * sBs;
    if (C) C += (size_t)z * sCs;

    const int tid = threadIdx.x;
    const int wid = tid >> 5;
    const int warpM = wid % WARPS_M;
    const int warpN = wid / WARPS_M;
    const int row0 = blockIdx.y * BM;
    const int col0 = blockIdx.x * BN;

    wmma::fragment<wmma::accumulator, 16, 16, 16, float> acc[FM][FN];
#pragma unroll
    for (int i = 0; i < FM; i++)
#pragma unroll
        for (int j = 0; j < FN; j++) wmma::fill_fragment(acc[i][j], 0.f);

    const int KB = K / BK;

    auto stage_in = [&](int kb, int buf) {
        bf16* st = smh + buf * STAGE;
        ld_tile_h<BM, BK, THREADS>(AH + (size_t)row0 * ldA + kb * BK, ldA, st, SA, tid);
        ld_tile_h<BM, BK, THREADS>(AL + (size_t)row0 * ldA + kb * BK, ldA, st + ASZ, SA, tid);
        if constexpr (BROW) {
            ld_tile_h<BK, BN, THREADS>(BH + (size_t)kb * BK * ldB + col0, ldB, st + 2 * ASZ, SB, tid);
            ld_tile_h<BK, BN, THREADS>(BL + (size_t)kb * BK * ldB + col0, ldB, st + 2 * ASZ + BSZ, SB, tid);
        } else {
            ld_tile_h<BN, BK, THREADS>(BH + (size_t)col0 * ldB + kb * BK, ldB, st + 2 * ASZ, SB, tid);
            ld_tile_h<BN, BK, THREADS>(BL + (size_t)col0 * ldB + kb * BK, ldB, st + 2 * ASZ + BSZ, SB, tid);
        }
    };

    stage_in(0, 0);
    cp_commit();

    for (int kb = 0; kb < KB; kb++) {
        if (kb + 1 < KB) stage_in(kb + 1, (kb + 1) & 1);
        cp_commit();
        cp_wait<1>();
        __syncthreads();

        const bf16* st = smh + (kb & 1) * STAGE;
        const bf16* AHt = st;
        const bf16* ALt = st + ASZ;
        const bf16* BHt = st + 2 * ASZ;
        const bf16* BLt = st + 2 * ASZ + BSZ;

#pragma unroll
        for (int kk = 0; kk < BK / 16; kk++) {
            wmma::fragment<wmma::matrix_a, 16, 16, 16, bf16, wmma::row_major> ah[FM], al[FM];
#pragma unroll
            for (int i = 0; i < FM; i++) {
                wmma::load_matrix_sync(ah[i], AHt + (warpM * WM + i * 16) * SA + kk * 16, SA);
                wmma::load_matrix_sync(al[i], ALt + (warpM * WM + i * 16) * SA + kk * 16, SA);
            }
            if constexpr (BROW) {
#pragma unroll
                for (int j = 0; j < FN; j++) {
                    wmma::fragment<wmma::matrix_b, 16, 16, 16, bf16, wmma::row_major> bh, bl;
                    wmma::load_matrix_sync(bh, BHt + kk * 16 * SB + warpN * WN + j * 16, SB);
                    wmma::load_matrix_sync(bl, BLt + kk * 16 * SB + warpN * WN + j * 16, SB);
#pragma unroll
                    for (int i = 0; i < FM; i++) {
                        wmma::mma_sync(acc[i][j], ah[i], bh, acc[i][j]);
                        wmma::mma_sync(acc[i][j], ah[i], bl, acc[i][j]);
                        wmma::mma_sync(acc[i][j], al[i], bh, acc[i][j]);
                    }
                }
            } else {
#pragma unroll
                for (int j = 0; j < FN; j++) {
                    wmma::fragment<wmma::matrix_b, 16, 16, 16, bf16, wmma::col_major> bh, bl;
                    wmma::load_matrix_sync(bh, BHt + (warpN * WN + j * 16) * SB + kk * 16, SB);
                    wmma::load_matrix_sync(bl, BLt + (warpN * WN + j * 16) * SB + kk * 16, SB);
#pragma unroll
                    for (int i = 0; i < FM; i++) {
                        wmma::mma_sync(acc[i][j], ah[i], bh, acc[i][j]);
                        wmma::mma_sync(acc[i][j], ah[i], bl, acc[i][j]);
                        wmma::mma_sync(acc[i][j], al[i], bh, acc[i][j]);
                    }
                }
            }
        }
        __syncthreads();
    }

    float* smf = reinterpret_cast<float*>(smh);
#pragma unroll
    for (int i = 0; i < FM; i++)
#pragma unroll
        for (int j = 0; j < FN; j++)
            wmma::store_matrix_sync(smf + (size_t)(warpM * WM + i * 16) * SC + warpN * WN + j * 16,
                                    acc[i][j], SC, wmma::mem_row_major);
    __syncthreads();

    constexpr int QUADS = BM * BN / 4;
#pragma unroll 4
    for (int qd = tid; qd < QUADS; qd += THREADS) {
        const int r = qd / (BN / 4);
        const int c4 = (qd - r * (BN / 4)) * 4;
        const int m = row0 + r;
        const int n = col0 + c4;
        float4 v = *reinterpret_cast<const float4*>(smf + r * SC + c4);

        if constexpr (EPI == EPI_CONVPOS) {
            float4 bb = *reinterpret_cast<const float4*>(bias + n);
            float4 p = *reinterpret_cast<const float4*>(aux1 + (size_t)(m & (SEQ - 1)) * EMB + n);
            v.x += bb.x + p.x; v.y += bb.y + p.y; v.z += bb.z + p.z; v.w += bb.w + p.w;
            *reinterpret_cast<float4*>(C + (size_t)m * N + n) = v;
        } else if constexpr (EPI == EPI_QKV) {
            float4 bb = *reinterpret_cast<const float4*>(bias + n);
            v.x += bb.x; v.y += bb.y; v.z += bb.z; v.w += bb.w;
            const int which = n / EMB;
            const int rr = n - which * EMB;
            const int head = rr >> 6;
            const int d = rr & 63;
            const int b = m >> 10, nl = m & (SEQ - 1);
            bf16* dh = (which == 0) ? o0h : ((which == 1) ? o1h : o2h);
            bf16* dl = (which == 0) ? o0l : ((which == 1) ? o1l : o2l);
            size_t off = ((size_t)(b * NHEAD + head) * SEQ + nl) * HD + d;
            split_store4(v, dh + off, dl + off);
        } else if constexpr (EPI == EPI_SREL) {
            const float rh = aux1[((size_t)z * SEQ + m) * GRID32 + (n >> 5)];
            const float* rw = aux2 + ((size_t)z * SEQ + m) * GRID32;
            v.x = v.x * scale + rh + rw[(n + 0) & 31];
            v.y = v.y * scale + rh + rw[(n + 1) & 31];
            v.z = v.z * scale + rh + rw[(n + 2) & 31];
            v.w = v.w * scale + rh + rw[(n + 3) & 31];
            *reinterpret_cast<float4*>(C + (size_t)m * N + n) = v;
        } else if constexpr (EPI == EPI_AV) {
            const int b = z / NHEAD;
            const int head = z - b * NHEAD;
            size_t off = ((size_t)(b * SEQ + m)) * EMB + head * HD + n;
            split_store4(v, o0h + off, o0l + off);
        } else if constexpr (EPI == EPI_BIASRES) {
            float4 bb = *reinterpret_cast<const float4*>(bias + n);
            float4 p = *reinterpret_cast<const float4*>(aux1 + (size_t)m * N + n);
            v.x += bb.x + p.x; v.y += bb.y + p.y; v.z += bb.z + p.z; v.w += bb.w + p.w;
            *reinterpret_cast<float4*>(C + (size_t)m * N + n) = v;
        } else if constexpr (EPI == EPI_GELU) {
            float4 bb = *reinterpret_cast<const float4*>(bias + n);
            v.x = 0.5f * (v.x + bb.x) * (1.f + erff((v.x + bb.x) * 0.70710678118654752f));
            v.y = 0.5f * (v.y + bb.y) * (1.f + erff((v.y + bb.y) * 0.70710678118654752f));
            v.z = 0.5f * (v.z + bb.z) * (1.f + erff((v.z + bb.z) * 0.70710678118654752f));
            v.w = 0.5f * (v.w + bb.w) * (1.f + erff((v.w + bb.w) * 0.70710678118654752f));
            split_store4(v, o0h + (size_t)m * N + n, o0l + (size_t)m * N + n);
        }
    }
}

constexpr int wg_smem_bytes(int BM, int BN, int BK, bool BROW)
{
    int ASZ = BM * (BK + 8);
    int BROWS = BROW ? BK : BN;
    int SB = BROW ? (BN + 8) : (BK + 8);
    int BSZ = BROWS * SB;
    return 2 * 2 * (ASZ + BSZ) * 2;
}

// ---------------- weight prep: split(+transpose) fp32 -> bf16 hi/lo [N,K] ----------------
struct PrepJob {
    const float* src;
    bf16* dh;
    bf16* dl;
    int K;
    int N;
    int trans;
};
struct Jobs8 { PrepJob j[8]; };

__global__ __launch_bounds__(256)
void prep_kernel(Jobs8 jobs)
{
    const PrepJob jb = jobs.j[blockIdx.z];
    __shared__ float t[32][33];
    const int x = threadIdx.x, y = threadIdx.y;
    if (jb.trans) {
        const int n0 = blockIdx.x * 32, k0 = blockIdx.y * 32;
        if (n0 >= jb.N || k0 >= jb.K) return;
#pragma unroll
        for (int i = y; i < 32; i += 8) t[i][x] = jb.src[(size_t)(k0 + i) * jb.N + n0 + x];
        __syncthreads();
#pragma unroll
        for (int i = y; i < 32; i += 8) {
            bf16 h, l;
            split1(t[x][i], h, l);
            size_t o = (size_t)(n0 + i) * jb.K + k0 + x;
            jb.dh[o] = h; jb.dl[o] = l;
        }
    } else {
        const int k0 = blockIdx.x * 32, n0 = blockIdx.y * 32;
        if (k0 >= jb.K || n0 >= jb.N) return;
#pragma unroll
        for (int i = y; i < 32; i += 8) {
            size_t o = (size_t)(n0 + i) * jb.K + k0 + x;
            bf16 h, l;
            split1(jb.src[o], h, l);
            jb.dh[o] = h; jb.dl[o] = l;
        }
    }
}

// ---------------- im2col (split output) ----------------
__global__ void im2col_kernel(const float* __restrict__ x,
                              bf16* __restrict__ colH, bf16* __restrict__ colL)
{
    int idx = blockIdx.x * blockDim.x + threadIdx.x;
    if (idx >= TOKENS * EMB) return;
    int m = idx / EMB, kk = idx - m * EMB;
    int b = m >> 10, p = m & 1023, ph = p >> 5, pw = p & 31;
    int c = kk >> 8, r = kk & 255, kh = r >> 4, kw = r & 15;
    float v = x[((size_t)(b * 3 + c) * 512 + (ph * 16 + kh)) * 512 + pw * 16 + kw];
    bf16 h, l;
    split1(v, h, l);
    colH[idx] = h; colL[idx] = l;
}

// ---------------- layernorm (split output planes) ----------------
__device__ __forceinline__ float warpReduceSum(float v)
{
#pragma unroll
    for (int o = 16; o; o >>= 1) v += __shfl_xor_sync(0xffffffffu, v, o);
    return v;
}

__global__ __launch_bounds__(256)
void ln_kernel(const float* __restrict__ in, const float* __restrict__ w,
               const float* __restrict__ b,
               bf16* __restrict__ outH, bf16* __restrict__ outL)
{
    __shared__ float sh[8];
    const int row = blockIdx.x;
    const int t = threadIdx.x;
    const float* x = in + (size_t)row * EMB;
    float v0 = x[t], v1 = x[t + 256], v2 = x[t + 512];
    float s = warpReduceSum(v0 + v1 + v2);
    if ((t & 31) == 0) sh[t >> 5] = s;
    __syncthreads();
    float mean = (sh[0] + sh[1] + sh[2] + sh[3] + sh[4] + sh[5] + sh[6] + sh[7]) * (1.f / EMB);
    float d0 = v0 - mean, d1 = v1 - mean, d2 = v2 - mean;
    __syncthreads();
    float s2 = warpReduceSum(d0 * d0 + d1 * d1 + d2 * d2);
    if ((t & 31) == 0) sh[t >> 5] = s2;
    __syncthreads();
    float var = (sh[0] + sh[1] + sh[2] + sh[3] + sh[4] + sh[5] + sh[6] + sh[7]) * (1.f / EMB);
    float rstd = rsqrtf(var + 1e-5f);
    bf16 h, l;
    size_t base = (size_t)row * EMB;
    float o0 = d0 * rstd * w[t] + b[t];
    float o1 = d1 * rstd * w[t + 256] + b[t + 256];
    float o2 = d2 * rstd * w[t + 512] + b[t + 512];
    split1(o0, h, l); outH[base + t] = h;       outL[base + t] = l;
    split1(o1, h, l); outH[base + t + 256] = h; outL[base + t + 256] = l;
    split1(o2, h, l); outH[base + t + 512] = h; outL[base + t + 512] = l;
}

// ---------------- decomposed rel-pos dot products ----------------
__global__ __launch_bounds__(64)
void rel_kernel(const bf16* __restrict__ qH, const bf16* __restrict__ qL,
                const float* __restrict__ rph, const float* __restrict__ rpw,
                float* __restrict__ relh, float* __restrict__ relw)
{
    const int bq = blockIdx.x;
    const int p = bq & (SEQ - 1);
    const int qh = p >> 5, qw = p & 31;
    __shared__ float qs[HD];
    const int t = threadIdx.x;
    qs[t] = __bfloat162float(qH[(size_t)bq * HD + t]) + __bfloat162float(qL[(size_t)bq * HD + t]);
    __syncthreads();
    const int kidx = t & 31;
    const float* tab = (t < 32) ? (rph + (qh - kidx + 31) * HD)
                                : (rpw + (qw - kidx + 31) * HD);
    float s = 0.f;
#pragma unroll
    for (int d = 0; d < HD; d++) s = fmaf(qs[d], tab[d], s);
    if (t < 32) relh[(size_t)bq * GRID32 + kidx] = s;
    else        relw[(size_t)bq * GRID32 + kidx] = s;
}

// ---------------- row softmax over SEQ=1024, writes split planes in place ----------------
__global__ __launch_bounds__(256)
void softmax_kernel(float* __restrict__ S)
{
    __shared__ float sh[8];
    const size_t row = blockIdx.x;
    float* p = S + row * SEQ;
    const int t = threadIdx.x;
    float v0 = p[t], v1 = p[t + 256], v2 = p[t + 512], v3 = p[t + 768];
    float mx = fmaxf(fmaxf(v0, v1), fmaxf(v2, v3));
#pragma unroll
    for (int o = 16; o; o >>= 1) mx = fmaxf(mx, __shfl_xor_sync(0xffffffffu, mx, o));
    if ((t & 31) == 0) sh[t >> 5] = mx;
    __syncthreads();
    mx = fmaxf(fmaxf(fmaxf(sh[0], sh[1]), fmaxf(sh[2], sh[3])),
               fmaxf(fmaxf(sh[4], sh[5]), fmaxf(sh[6], sh[7])));
    v0 = __expf(v0 - mx); v1 = __expf(v1 - mx);
    v2 = __expf(v2 - mx); v3 = __expf(v3 - mx);
    float s = warpReduceSum(v0 + v1 + v2 + v3);
    __syncthreads();
    if ((t & 31) == 0) sh[t >> 5] = s;
    __syncthreads();
    float inv = 1.f / (sh[0] + sh[1] + sh[2] + sh[3] + sh[4] + sh[5] + sh[6] + sh[7]);
    // rewrite row as bf16 planes: [0,1024) hi, [1024,2048) lo (same 4 KB)
    bf16* ph = reinterpret_cast<bf16*>(p);
    bf16* pl = ph + SEQ;
    bf16 h, l;
    split1(v0 * inv, h, l); ph[t] = h;       pl[t] = l;
    split1(v1 * inv, h, l); ph[t + 256] = h; pl[t + 256] = l;
    split1(v2 * inv, h, l); ph[t + 512] = h; pl[t + 512] = l;
    split1(v3 * inv, h, l); ph[t + 768] = h; pl[t + 768] = l;
}

// ---------------- host orchestration ----------------
extern "C" void kernel_launch(void* const* d_in, const int* in_sizes, int n_in,
                              void* d_out, int out_size)
{
    const float* x      = (const float*)d_in[0];
    const float* conv_w = (const float*)d_in[1];
    const float* conv_b = (const float*)d_in[2];
    const float* pos    = (const float*)d_in[3];
    const float* ln1_w  = (const float*)d_in[4];
    const float* ln1_b  = (const float*)d_in[5];
    const float* qkv_w  = (const float*)d_in[6];
    const float* qkv_b  = (const float*)d_in[7];
    const float* proj_w = (const float*)d_in[8];
    const float* proj_b = (const float*)d_in[9];
    const float* rph    = (const float*)d_in[10];
    const float* rpw    = (const float*)d_in[11];
    const float* ln2_w  = (const float*)d_in[12];
    const float* ln2_b  = (const float*)d_in[13];
    const float* fc1_w  = (const float*)d_in[14];
    const float* fc1_b  = (const float*)d_in[15];
    const float* fc2_w  = (const float*)d_in[16];
    const float* fc2_b  = (const float*)d_in[17];

    float *h, *relh, *relw, *S;
    bf16 *colH, *colL, *xnH, *xnL, *qH, *qL, *kH, *kL, *vH, *vL, *attnH, *attnL, *mlpH, *mlpL;
    bf16 *cwTH, *cwTL, *qkvTH, *qkvTL, *projTH, *projTL, *fc1TH, *fc1TL, *fc2TH, *fc2TL;
    cudaGetSymbolAddress((void**)&h, g_h);
    cudaGetSymbolAddress((void**)&relh, g_relh);
    cudaGetSymbolAddress((void**)&relw, g_relw);
    cudaGetSymbolAddress((void**)&S, g_S);
    cudaGetSymbolAddress((void**)&colH, g_colH);   cudaGetSymbolAddress((void**)&colL, g_colL);
    cudaGetSymbolAddress((void**)&xnH, g_xnH);     cudaGetSymbolAddress((void**)&xnL, g_xnL);
    cudaGetSymbolAddress((void**)&qH, g_qH);       cudaGetSymbolAddress((void**)&qL, g_qL);
    cudaGetSymbolAddress((void**)&kH, g_kH);       cudaGetSymbolAddress((void**)&kL, g_kL);
    cudaGetSymbolAddress((void**)&vH, g_vH);       cudaGetSymbolAddress((void**)&vL, g_vL);
    cudaGetSymbolAddress((void**)&attnH, g_attnH); cudaGetSymbolAddress((void**)&attnL, g_attnL);
    cudaGetSymbolAddress((void**)&mlpH, g_mlpH);   cudaGetSymbolAddress((void**)&mlpL, g_mlpL);
    cudaGetSymbolAddress((void**)&cwTH, g_cwTH);   cudaGetSymbolAddress((void**)&cwTL, g_cwTL);
    cudaGetSymbolAddress((void**)&qkvTH, g_qkvTH); cudaGetSymbolAddress((void**)&qkvTL, g_qkvTL);
    cudaGetSymbolAddress((void**)&projTH, g_projTH); cudaGetSymbolAddress((void**)&projTL, g_projTL);
    cudaGetSymbolAddress((void**)&fc1TH, g_fc1TH); cudaGetSymbolAddress((void**)&fc1TL, g_fc1TL);
    cudaGetSymbolAddress((void**)&fc2TH, g_fc2TH); cudaGetSymbolAddress((void**)&fc2TL, g_fc2TL);

    constexpr int SM_BIG = wg_smem_bytes(128, 128, 32, false);   // 81920 -> 2 CTAs/SM
    constexpr int SM_AV  = wg_smem_bytes(128, 64, 32, true);     // 59392 -> 2 CTAs/SM

    cudaFuncSetAttribute((const void*)wgemm<128,128,32,32,64,EPI_CONVPOS,false>,
                         cudaFuncAttributeMaxDynamicSharedMemorySize, SM_BIG);
    cudaFuncSetAttribute((const void*)wgemm<128,128,32,32,64,EPI_QKV,false>,
                         cudaFuncAttributeMaxDynamicSharedMemorySize, SM_BIG);
    cudaFuncSetAttribute((const void*)wgemm<128,128,32,32,64,EPI_SREL,false>,
                         cudaFuncAttributeMaxDynamicSharedMemorySize, SM_BIG);
    cudaFuncSetAttribute((const void*)wgemm<128,64,32,32,32,EPI_AV,true>,
                         cudaFuncAttributeMaxDynamicSharedMemorySize, SM_AV);
    cudaFuncSetAttribute((const void*)wgemm<128,128,32,32,64,EPI_BIASRES,false>,
                         cudaFuncAttributeMaxDynamicSharedMemorySize, SM_BIG);
    cudaFuncSetAttribute((const void*)wgemm<128,128,32,32,64,EPI_GELU,false>,
                         cudaFuncAttributeMaxDynamicSharedMemorySize, SM_BIG);

    const float scale = 0.125f;  // HD^-0.5
    const dim3 tb(32, 8);

    // ---- weight prep ----
    {
        Jobs8 J{};
        for (int l = 0; l < 4; l++) {
            J.j[l]     = { qkv_w  + (size_t)l * EMB * 3 * EMB,
                           qkvTH  + (size_t)l * 3 * EMB * EMB,
                           qkvTL  + (size_t)l * 3 * EMB * EMB, EMB, 3 * EMB, 1 };
            J.j[4 + l] = { proj_w + (size_t)l * EMB * EMB,
                           projTH + (size_t)l * EMB * EMB,
                           projTL + (size_t)l * EMB * EMB, EMB, EMB, 1 };
        }
        prep_kernel<<<dim3(3 * EMB / 32, EMB / 32, 8), tb>>>(J);
    }
    {
        Jobs8 J{};
        for (int l = 0; l < 4; l++)
            J.j[l] = { fc1_w + (size_t)l * EMB * MLPD,
                       fc1TH + (size_t)l * MLPD * EMB,
                       fc1TL + (size_t)l * MLPD * EMB, EMB, MLPD, 1 };
        prep_kernel<<<dim3(MLPD / 32, EMB / 32, 4), tb>>>(J);
    }
    {
        Jobs8 J{};
        for (int l = 0; l < 4; l++)
            J.j[l] = { fc2_w + (size_t)l * MLPD * EMB,
                       fc2TH + (size_t)l * EMB * MLPD,
                       fc2TL + (size_t)l * EMB * MLPD, MLPD, EMB, 1 };
        prep_kernel<<<dim3(EMB / 32, MLPD / 32, 4), tb>>>(J);
    }
    {
        Jobs8 J{};
        J.j[0] = { conv_w, cwTH, cwTL, EMB, EMB, 0 };
        prep_kernel<<<dim3(EMB / 32, EMB / 32, 1), tb>>>(J);
    }

    im2col_kernel<<<(TOKENS * EMB + 255) / 256, 256>>>(x, colH, colL);

    wgemm<128,128,32,32,64,EPI_CONVPOS,false><<<dim3(EMB/128, TOKENS/128), 256, SM_BIG>>>(
        colH, colL, EMB, cwTH, cwTL, EMB, h, EMB, EMB, 0, 0, 0,
        conv_b, pos, nullptr, nullptr, nullptr, nullptr, nullptr, nullptr, nullptr, 0.f);

    for (int i = 0; i < 4; i++) {
        ln_kernel<<<TOKENS, 256>>>(h, ln1_w + i * EMB, ln1_b + i * EMB, xnH, xnL);

        wgemm<128,128,32,32,64,EPI_QKV,false><<<dim3(3*EMB/128, TOKENS/128), 256, SM_BIG>>>(
            xnH, xnL, EMB,
            qkvTH + (size_t)i * 3 * EMB * EMB, qkvTL + (size_t)i * 3 * EMB * EMB, EMB,
            nullptr, 3 * EMB, EMB, 0, 0, 0,
            qkv_b + (size_t)i * 3 * EMB, nullptr, nullptr,
            qH, qL, kH, kL, vH, vL, 0.f);

        rel_kernel<<<BHEADS * SEQ, 64>>>(qH, qL,
                                         rph + (size_t)i * 63 * HD, rpw + (size_t)i * 63 * HD,
                                         relh, relw);

        // S = scale * q @ k^T + rel_h + rel_w  (batched over 48 bh; K=64 -> 2 k-blocks)
        wgemm<128,128,32,32,64,EPI_SREL,false><<<dim3(SEQ/128, SEQ/128, BHEADS), 256, SM_BIG>>>(
            qH, qL, HD, kH, kL, HD, S, SEQ, HD,
            (size_t)SEQ * HD, (size_t)SEQ * HD, (size_t)SEQ * SEQ,
            nullptr, relh, relw,
            nullptr, nullptr, nullptr, nullptr, nullptr, nullptr, scale);

        softmax_kernel<<<BHEADS * SEQ, 256>>>(S);

        // O = P @ v ; P planes live inside g_S rows (hi at +0, lo at +1024, row stride 2048)
        wgemm<128,64,32,32,32,EPI_AV,true><<<dim3(1, SEQ/128, BHEADS), 256, SM_AV>>>(
            (const bf16*)S, (const bf16*)S + SEQ, 2 * SEQ,
            vH, vL, HD,
            nullptr, HD, SEQ,
            (size_t)SEQ * 2 * SEQ, (size_t)SEQ * HD, 0,
            nullptr, nullptr, nullptr,
            attnH, attnL, nullptr, nullptr, nullptr, nullptr, 0.f);

        wgemm<128,128,32,32,64,EPI_BIASRES,false><<<dim3(EMB/128, TOKENS/128), 256, SM_BIG>>>(
            attnH, attnL, EMB,
            projTH + (size_t)i * EMB * EMB, projTL + (size_t)i * EMB * EMB, EMB,
            h, EMB, EMB, 0, 0, 0,
            proj_b + (size_t)i * EMB, h, nullptr,
            nullptr, nullptr, nullptr, nullptr, nullptr, nullptr, 0.f);

        ln_kernel<<<TOKENS, 256>>>(h, ln2_w + i * EMB, ln2_b + i * EMB, xnH, xnL);

        wgemm<128,128,32,32,64,EPI_GELU,false><<<dim3(MLPD/128, TOKENS/128), 256, SM_BIG>>>(
            xnH, xnL, EMB,
            fc1TH + (size_t)i * MLPD * EMB, fc1TL + (size_t)i * MLPD * EMB, EMB,
            nullptr, MLPD, EMB, 0, 0, 0,
            fc1_b + (size_t)i * MLPD, nullptr, nullptr,
            mlpH, mlpL, nullptr, nullptr, nullptr, nullptr, 0.f);

        float* dst = (i == 3) ? (float*)d_out : h;
        wgemm<128,128,32,32,64,EPI_BIASRES,false><<<dim3(EMB/128, TOKENS/128), 256, SM_BIG>>>(
            mlpH, mlpL, MLPD,
            fc2TH + (size_t)i * EMB * MLPD, fc2TL + (size_t)i * EMB * MLPD, MLPD,
            dst, EMB, MLPD, 0, 0, 0,
            fc2_b + (size_t)i * EMB, h, nullptr,
            nullptr, nullptr, nullptr, nullptr, nullptr, nullptr, 0.f);
    }
}

// round 14
// speedup vs baseline: 1.3858x; 1.2365x over previous
#include <cuda_runtime.h>
#include <cuda_fp16.h>
#include <math.h>
#include <stdint.h>
#include <mma.h>

using namespace nvcuda;

// ---------------- problem constants ----------------
#define TOKENS 4096      // B(4) * 32 * 32
#define EMB    768
#define NHEAD  12
#define HD     64
#define SEQ    1024      // tokens per image
#define BHEADS 48        // B * NHEAD
#define MLPD   3072
#define GRID32 32

typedef __half hf;

// ---------------- scratch (device globals; no allocs allowed) ----------------
__device__ float g_h[TOKENS * EMB];
__device__ float g_relh[BHEADS * SEQ * GRID32];
__device__ float g_relw[BHEADS * SEQ * GRID32];
__device__ hf    g_S[(size_t)BHEADS * SEQ * SEQ];   // fp16 logits; softmax rewrites as fp16 probs in place

// activation planes (hi/lo split where needed; q/k/v single-plane)
__device__ hf g_colH[TOKENS * EMB],  g_colL[TOKENS * EMB];
__device__ hf g_xnH[TOKENS * EMB],   g_xnL[TOKENS * EMB];
__device__ hf g_q[BHEADS * SEQ * HD];
__device__ hf g_k[BHEADS * SEQ * HD];
__device__ hf g_v[BHEADS * SEQ * HD];
__device__ hf g_attnH[TOKENS * EMB], g_attnL[TOKENS * EMB];
__device__ hf g_mlpH[TOKENS * MLPD], g_mlpL[TOKENS * MLPD];

// weight planes, [N,K] K-major (lo planes only where the GEMM uses NB=2)
__device__ hf g_cwTH[EMB * EMB],          g_cwTL[EMB * EMB];
__device__ hf g_qkvTH[4 * 3 * EMB * EMB];
__device__ hf g_projTH[4 * EMB * EMB],    g_projTL[4 * EMB * EMB];
__device__ hf g_fc1TH[4 * MLPD * EMB];
__device__ hf g_fc2TH[4 * EMB * MLPD];

enum { EPI_CONVPOS = 1, EPI_QKV = 2, EPI_SREL = 3, EPI_AV = 4, EPI_BIASRES = 5, EPI_GELU = 6 };

// ---------------- helpers ----------------
__device__ __forceinline__ void split1(float x, hf& h, hf& l)
{
    h = __float2half_rn(x);
    l = __float2half_rn(x - __half2float(h));
}

__device__ __forceinline__ void split_store4(float4 v, hf* ph, hf* pl)
{
    hf h0, h1, h2, h3, l0, l1, l2, l3;
    split1(v.x, h0, l0); split1(v.y, h1, l1);
    split1(v.z, h2, l2); split1(v.w, h3, l3);
    reinterpret_cast<__half2*>(ph)[0] = __halves2half2(h0, h1);
    reinterpret_cast<__half2*>(ph)[1] = __halves2half2(h2, h3);
    reinterpret_cast<__half2*>(pl)[0] = __halves2half2(l0, l1);
    reinterpret_cast<__half2*>(pl)[1] = __halves2half2(l2, l3);
}

__device__ __forceinline__ void store4h(float4 v, hf* p)
{
    reinterpret_cast<__half2*>(p)[0] = __floats2half2_rn(v.x, v.y);
    reinterpret_cast<__half2*>(p)[1] = __floats2half2_rn(v.z, v.w);
}

__device__ __forceinline__ uint32_t smem_u32(const void* p)
{
    return (uint32_t)__cvta_generic_to_shared(p);
}

__device__ __forceinline__ void cp16(uint32_t dst, const void* src)
{
    asm volatile("cp.async.cg.shared.global [%0], [%1], 16;\n" :: "r"(dst), "l"(src));
}
__device__ __forceinline__ void cp_commit()
{
    asm volatile("cp.async.commit_group;\n" ::: "memory");
}
template <int N>
__device__ __forceinline__ void cp_wait()
{
    asm volatile("cp.async.wait_group %0;\n" :: "n"(N) : "memory");
}

// stage NROWS x CFL halves from global (row stride ld halves) into smem (row stride ss halves)
template <int NROWS, int CFL, int THREADS>
__device__ __forceinline__ void ld_tile_h(const hf* __restrict__ g, int ld,
                                          hf* __restrict__ s, int ss, int tid)
{
    constexpr int CH = NROWS * (CFL / 8);      // 16-byte chunks
    static_assert(CH % THREADS == 0, "chunk mapping");
#pragma unroll
    for (int i = 0; i < CH / THREADS; i++) {
        int lin = i * THREADS + tid;
        int r = lin / (CFL / 8);
        int c = (lin - r * (CFL / 8)) * 8;
        cp16(smem_u32(s + r * ss + c), g + (size_t)r * ld + c);
    }
}

// ---------------- split-fp16 wmma GEMM with fused epilogues ----------------
// NA/NB = planes staged for A/B (2 = hi+lo split, 1 = hi only).
// MMAs: ah*bh  (+ ah*bl if NB==2)  (+ al*bh if NA==2).  al*bl always dropped.
// BROW=false: B planes [N,K] row-major (wmma col_major). BROW=true: [K,N] row-major.
template <int BM, int BN, int BK, int WM, int WN, int EPI, bool BROW, int NA, int NB>
__global__ __launch_bounds__((BM / WM) * (BN / WN) * 32, 2)
void wgemm(const hf* __restrict__ AH, const hf* __restrict__ AL, int ldA,
           const hf* __restrict__ BH, const hf* __restrict__ BL, int ldB,
           float* __restrict__ C, int N, int K,
           size_t sAs, size_t sBs, size_t sCs,
           const float* __restrict__ bias,
           const float* __restrict__ aux1, const float* __restrict__ aux2,
           hf* __restrict__ o0h, hf* __restrict__ o0l,
           hf* __restrict__ o1h, hf* __restrict__ o2h,
           float scale)
{
    constexpr int WARPS_M = BM / WM;
    constexpr int WARPS_N = BN / WN;
    constexpr int THREADS = WARPS_M * WARPS_N * 32;
    constexpr int FM = WM / 16, FN = WN / 16;
    constexpr int SA = BK + 8;
    constexpr int SB = BROW ? (BN + 8) : (BK + 8);
    constexpr int BROWS = BROW ? BK : BN;
    constexpr int ASZ = BM * SA;
    constexpr int BSZ = BROWS * SB;
    constexpr int STAGE = NA * ASZ + NB * BSZ;     // halves
    constexpr int SC = BN + 8;

    extern __shared__ hf smh[];

    const int z = blockIdx.z;
    AH += (size_t)z * sAs;
    if (NA == 2) AL += (size_t)z * sAs;
    BH += (size_t)z * sBs;
    if (NB == 2) BL += (size_t)z * sBs;
    if (C) C += (size_t)z * sCs;
    hf* o0h_z = o0h;
    if (EPI == EPI_SREL) o0h_z += (size_t)z * sCs;

    const int tid = threadIdx.x;
    const int wid = tid >> 5;
    const int warpM = wid % WARPS_M;
    const int warpN = wid / WARPS_M;
    const int row0 = blockIdx.y * BM;
    const int col0 = blockIdx.x * BN;

    wmma::fragment<wmma::accumulator, 16, 16, 16, float> acc[FM][FN];
#pragma unroll
    for (int i = 0; i < FM; i++)
#pragma unroll
        for (int j = 0; j < FN; j++) wmma::fill_fragment(acc[i][j], 0.f);

    const int KB = K / BK;

    auto stage_in = [&](int kb, int buf) {
        hf* st = smh + buf * STAGE;
        ld_tile_h<BM, BK, THREADS>(AH + (size_t)row0 * ldA + kb * BK, ldA, st, SA, tid);
        if constexpr (NA == 2)
            ld_tile_h<BM, BK, THREADS>(AL + (size_t)row0 * ldA + kb * BK, ldA, st + ASZ, SA, tid);
        hf* bst = st + NA * ASZ;
        if constexpr (BROW) {
            ld_tile_h<BK, BN, THREADS>(BH + (size_t)kb * BK * ldB + col0, ldB, bst, SB, tid);
            if constexpr (NB == 2)
                ld_tile_h<BK, BN, THREADS>(BL + (size_t)kb * BK * ldB + col0, ldB, bst + BSZ, SB, tid);
        } else {
            ld_tile_h<BN, BK, THREADS>(BH + (size_t)col0 * ldB + kb * BK, ldB, bst, SB, tid);
            if constexpr (NB == 2)
                ld_tile_h<BN, BK, THREADS>(BL + (size_t)col0 * ldB + kb * BK, ldB, bst + BSZ, SB, tid);
        }
    };

    stage_in(0, 0);
    cp_commit();

    for (int kb = 0; kb < KB; kb++) {
        if (kb + 1 < KB) stage_in(kb + 1, (kb + 1) & 1);
        cp_commit();
        cp_wait<1>();
        __syncthreads();

        const hf* st = smh + (kb & 1) * STAGE;
        const hf* AHt = st;
        const hf* ALt = st + ASZ;
        const hf* BHt = st + NA * ASZ;
        const hf* BLt = BHt + BSZ;

#pragma unroll
        for (int kk = 0; kk < BK / 16; kk++) {
            wmma::fragment<wmma::matrix_a, 16, 16, 16, hf, wmma::row_major> ah[FM], al[FM];
#pragma unroll
            for (int i = 0; i < FM; i++) {
                wmma::load_matrix_sync(ah[i], AHt + (warpM * WM + i * 16) * SA + kk * 16, SA);
                if constexpr (NA == 2)
                    wmma::load_matrix_sync(al[i], ALt + (warpM * WM + i * 16) * SA + kk * 16, SA);
            }
            if constexpr (BROW) {
#pragma unroll
                for (int j = 0; j < FN; j++) {
                    wmma::fragment<wmma::matrix_b, 16, 16, 16, hf, wmma::row_major> bh, bl;
                    wmma::load_matrix_sync(bh, BHt + kk * 16 * SB + warpN * WN + j * 16, SB);
                    if constexpr (NB == 2)
                        wmma::load_matrix_sync(bl, BLt + kk * 16 * SB + warpN * WN + j * 16, SB);
#pragma unroll
                    for (int i = 0; i < FM; i++) {
                        wmma::mma_sync(acc[i][j], ah[i], bh, acc[i][j]);
                        if constexpr (NB == 2) wmma::mma_sync(acc[i][j], ah[i], bl, acc[i][j]);
                        if constexpr (NA == 2) wmma::mma_sync(acc[i][j], al[i], bh, acc[i][j]);
                    }
                }
            } else {
#pragma unroll
                for (int j = 0; j < FN; j++) {
                    wmma::fragment<wmma::matrix_b, 16, 16, 16, hf, wmma::col_major> bh, bl;
                    wmma::load_matrix_sync(bh, BHt + (warpN * WN + j * 16) * SB + kk * 16, SB);
                    if constexpr (NB == 2)
                        wmma::load_matrix_sync(bl, BLt + (warpN * WN + j * 16) * SB + kk * 16, SB);
#pragma unroll
                    for (int i = 0; i < FM; i++) {
                        wmma::mma_sync(acc[i][j], ah[i], bh, acc[i][j]);
                        if constexpr (NB == 2) wmma::mma_sync(acc[i][j], ah[i], bl, acc[i][j]);
                        if constexpr (NA == 2) wmma::mma_sync(acc[i][j], al[i], bh, acc[i][j]);
                    }
                }
            }
        }
        __syncthreads();
    }

    float* smf = reinterpret_cast<float*>(smh);
#pragma unroll
    for (int i = 0; i < FM; i++)
#pragma unroll
        for (int j = 0; j < FN; j++)
            wmma::store_matrix_sync(smf + (size_t)(warpM * WM + i * 16) * SC + warpN * WN + j * 16,
                                    acc[i][j], SC, wmma::mem_row_major);
    __syncthreads();

    constexpr int QUADS = BM * BN / 4;
#pragma unroll 4
    for (int qd = tid; qd < QUADS; qd += THREADS) {
        const int r = qd / (BN / 4);
        const int c4 = (qd - r * (BN / 4)) * 4;
        const int m = row0 + r;
        const int n = col0 + c4;
        float4 v = *reinterpret_cast<const float4*>(smf + r * SC + c4);

        if constexpr (EPI == EPI_CONVPOS) {
            float4 bb = *reinterpret_cast<const float4*>(bias + n);
            float4 p = *reinterpret_cast<const float4*>(aux1 + (size_t)(m & (SEQ - 1)) * EMB + n);
            v.x += bb.x + p.x; v.y += bb.y + p.y; v.z += bb.z + p.z; v.w += bb.w + p.w;
            *reinterpret_cast<float4*>(C + (size_t)m * N + n) = v;
        } else if constexpr (EPI == EPI_QKV) {
            float4 bb = *reinterpret_cast<const float4*>(bias + n);
            v.x += bb.x; v.y += bb.y; v.z += bb.z; v.w += bb.w;
            const int which = n / EMB;
            const int rr = n - which * EMB;
            const int head = rr >> 6;
            const int d = rr & 63;
            const int b = m >> 10, nl = m & (SEQ - 1);
            hf* dst = (which == 0) ? o0h : ((which == 1) ? o1h : o2h);
            store4h(v, dst + ((size_t)(b * NHEAD + head) * SEQ + nl) * HD + d);
        } else if constexpr (EPI == EPI_SREL) {
            const float rh = aux1[((size_t)z * SEQ + m) * GRID32 + (n >> 5)];
            const float* rw = aux2 + ((size_t)z * SEQ + m) * GRID32;
            v.x = v.x * scale + rh + rw[(n + 0) & 31];
            v.y = v.y * scale + rh + rw[(n + 1) & 31];
            v.z = v.z * scale + rh + rw[(n + 2) & 31];
            v.w = v.w * scale + rh + rw[(n + 3) & 31];
            store4h(v, o0h_z + (size_t)m * N + n);
        } else if constexpr (EPI == EPI_AV) {
            const int b = z / NHEAD;
            const int head = z - b * NHEAD;
            size_t off = ((size_t)(b * SEQ + m)) * EMB + head * HD + n;
            split_store4(v, o0h + off, o0l + off);
        } else if constexpr (EPI == EPI_BIASRES) {
            float4 bb = *reinterpret_cast<const float4*>(bias + n);
            float4 p = *reinterpret_cast<const float4*>(aux1 + (size_t)m * N + n);
            v.x += bb.x + p.x; v.y += bb.y + p.y; v.z += bb.z + p.z; v.w += bb.w + p.w;
            *reinterpret_cast<float4*>(C + (size_t)m * N + n) = v;
        } else if constexpr (EPI == EPI_GELU) {
            float4 bb = *reinterpret_cast<const float4*>(bias + n);
            v.x = 0.5f * (v.x + bb.x) * (1.f + erff((v.x + bb.x) * 0.70710678118654752f));
            v.y = 0.5f * (v.y + bb.y) * (1.f + erff((v.y + bb.y) * 0.70710678118654752f));
            v.z = 0.5f * (v.z + bb.z) * (1.f + erff((v.z + bb.z) * 0.70710678118654752f));
            v.w = 0.5f * (v.w + bb.w) * (1.f + erff((v.w + bb.w) * 0.70710678118654752f));
            split_store4(v, o0h + (size_t)m * N + n, o0l + (size_t)m * N + n);
        }
    }
}

constexpr int wg_smem_bytes(int BM, int BN, int BK, bool BROW, int NA, int NB)
{
    int SA = BK + 8;
    int SB = BROW ? (BN + 8) : (BK + 8);
    int BROWS = BROW ? BK : BN;
    int pipe = 2 * (NA * BM * SA + NB * BROWS * SB) * 2;
    int cst = BM * (BN + 8) * 4;
    return pipe > cst ? pipe : cst;
}

// ---------------- weight prep: split(+transpose) fp32 -> fp16 hi(/lo) [N,K] ----------------
struct PrepJob {
    const float* src;
    hf* dh;
    hf* dl;       // nullptr -> hi plane only
    int K;
    int N;
    int trans;
};
struct Jobs8 { PrepJob j[8]; };

__global__ __launch_bounds__(256)
void prep_kernel(Jobs8 jobs)
{
    const PrepJob jb = jobs.j[blockIdx.z];
    __shared__ float t[32][33];
    const int x = threadIdx.x, y = threadIdx.y;
    if (jb.trans) {
        const int n0 = blockIdx.x * 32, k0 = blockIdx.y * 32;
        if (n0 >= jb.N || k0 >= jb.K) return;
#pragma unroll
        for (int i = y; i < 32; i += 8) t[i][x] = jb.src[(size_t)(k0 + i) * jb.N + n0 + x];
        __syncthreads();
#pragma unroll
        for (int i = y; i < 32; i += 8) {
            hf h, l;
            split1(t[x][i], h, l);
            size_t o = (size_t)(n0 + i) * jb.K + k0 + x;
            jb.dh[o] = h;
            if (jb.dl) jb.dl[o] = l;
        }
    } else {
        const int k0 = blockIdx.x * 32, n0 = blockIdx.y * 32;
        if (k0 >= jb.K || n0 >= jb.N) return;
#pragma unroll
        for (int i = y; i < 32; i += 8) {
            size_t o = (size_t)(n0 + i) * jb.K + k0 + x;
            hf h, l;
            split1(jb.src[o], h, l);
            jb.dh[o] = h;
            if (jb.dl) jb.dl[o] = l;
        }
    }
}

// ---------------- im2col (split output) ----------------
__global__ void im2col_kernel(const float* __restrict__ x,
                              hf* __restrict__ colH, hf* __restrict__ colL)
{
    int idx = blockIdx.x * blockDim.x + threadIdx.x;
    if (idx >= TOKENS * EMB) return;
    int m = idx / EMB, kk = idx - m * EMB;
    int b = m >> 10, p = m & 1023, ph = p >> 5, pw = p & 31;
    int c = kk >> 8, r = kk & 255, kh = r >> 4, kw = r & 15;
    float v = x[((size_t)(b * 3 + c) * 512 + (ph * 16 + kh)) * 512 + pw * 16 + kw];
    hf h, l;
    split1(v, h, l);
    colH[idx] = h; colL[idx] = l;
}

// ---------------- layernorm (split output planes) ----------------
__device__ __forceinline__ float warpReduceSum(float v)
{
#pragma unroll
    for (int o = 16; o; o >>= 1) v += __shfl_xor_sync(0xffffffffu, v, o);
    return v;
}

__global__ __launch_bounds__(256)
void ln_kernel(const float* __restrict__ in, const float* __restrict__ w,
               const float* __restrict__ b,
               hf* __restrict__ outH, hf* __restrict__ outL)
{
    __shared__ float sh[8];
    const int row = blockIdx.x;
    const int t = threadIdx.x;
    const float* x = in + (size_t)row * EMB;
    float v0 = x[t], v1 = x[t + 256], v2 = x[t + 512];
    float s = warpReduceSum(v0 + v1 + v2);
    if ((t & 31) == 0) sh[t >> 5] = s;
    __syncthreads();
    float mean = (sh[0] + sh[1] + sh[2] + sh[3] + sh[4] + sh[5] + sh[6] + sh[7]) * (1.f / EMB);
    float d0 = v0 - mean, d1 = v1 - mean, d2 = v2 - mean;
    __syncthreads();
    float s2 = warpReduceSum(d0 * d0 + d1 * d1 + d2 * d2);
    if ((t & 31) == 0) sh[t >> 5] = s2;
    __syncthreads();
    float var = (sh[0] + sh[1] + sh[2] + sh[3] + sh[4] + sh[5] + sh[6] + sh[7]) * (1.f / EMB);
    float rstd = rsqrtf(var + 1e-5f);
    hf h, l;
    size_t base = (size_t)row * EMB;
    float o0 = d0 * rstd * w[t] + b[t];
    float o1 = d1 * rstd * w[t + 256] + b[t + 256];
    float o2 = d2 * rstd * w[t + 512] + b[t + 512];
    split1(o0, h, l); outH[base + t] = h;       outL[base + t] = l;
    split1(o1, h, l); outH[base + t + 256] = h; outL[base + t + 256] = l;
    split1(o2, h, l); outH[base + t + 512] = h; outL[base + t + 512] = l;
}

// ---------------- decomposed rel-pos dot products (fp16 q) ----------------
__global__ __launch_bounds__(64)
void rel_kernel(const hf* __restrict__ q,
                const float* __restrict__ rph, const float* __restrict__ rpw,
                float* __restrict__ relh, float* __restrict__ relw)
{
    const int bq = blockIdx.x;
    const int p = bq & (SEQ - 1);
    const int qh = p >> 5, qw = p & 31;
    __shared__ float qs[HD];
    const int t = threadIdx.x;
    qs[t] = __half2float(q[(size_t)bq * HD + t]);
    __syncthreads();
    const int kidx = t & 31;
    const float* tab = (t < 32) ? (rph + (qh - kidx + 31) * HD)
                                : (rpw + (qw - kidx + 31) * HD);
    float s = 0.f;
#pragma unroll
    for (int d = 0; d < HD; d++) s = fmaf(qs[d], tab[d], s);
    if (t < 32) relh[(size_t)bq * GRID32 + kidx] = s;
    else        relw[(size_t)bq * GRID32 + kidx] = s;
}

// ---------------- row softmax over SEQ=1024 fp16 logits -> fp16 probs in place ----------------
__global__ __launch_bounds__(256)
void softmax_kernel(hf* __restrict__ S)
{
    __shared__ float sh[8];
    const size_t row = blockIdx.x;
    hf* p = S + row * SEQ;
    const int t = threadIdx.x;
    float v0 = __half2float(p[t]);
    float v1 = __half2float(p[t + 256]);
    float v2 = __half2float(p[t + 512]);
    float v3 = __half2float(p[t + 768]);
    float mx = fmaxf(fmaxf(v0, v1), fmaxf(v2, v3));
#pragma unroll
    for (int o = 16; o; o >>= 1) mx = fmaxf(mx, __shfl_xor_sync(0xffffffffu, mx, o));
    if ((t & 31) == 0) sh[t >> 5] = mx;
    __syncthreads();
    mx = fmaxf(fmaxf(fmaxf(sh[0], sh[1]), fmaxf(sh[2], sh[3])),
               fmaxf(fmaxf(sh[4], sh[5]), fmaxf(sh[6], sh[7])));
    v0 = __expf(v0 - mx); v1 = __expf(v1 - mx);
    v2 = __expf(v2 - mx); v3 = __expf(v3 - mx);
    float s = warpReduceSum(v0 + v1 + v2 + v3);
    __syncthreads();
    if ((t & 31) == 0) sh[t >> 5] = s;
    __syncthreads();
    float inv = 1.f / (sh[0] + sh[1] + sh[2] + sh[3] + sh[4] + sh[5] + sh[6] + sh[7]);
    p[t]       = __float2half_rn(v0 * inv);
    p[t + 256] = __float2half_rn(v1 * inv);
    p[t + 512] = __float2half_rn(v2 * inv);
    p[t + 768] = __float2half_rn(v3 * inv);
}

// ---------------- host orchestration ----------------
extern "C" void kernel_launch(void* const* d_in, const int* in_sizes, int n_in,
                              void* d_out, int out_size)
{
    const float* x      = (const float*)d_in[0];
    const float* conv_w = (const float*)d_in[1];
    const float* conv_b = (const float*)d_in[2];
    const float* pos    = (const float*)d_in[3];
    const float* ln1_w  = (const float*)d_in[4];
    const float* ln1_b  = (const float*)d_in[5];
    const float* qkv_w  = (const float*)d_in[6];
    const float* qkv_b  = (const float*)d_in[7];
    const float* proj_w = (const float*)d_in[8];
    const float* proj_b = (const float*)d_in[9];
    const float* rph    = (const float*)d_in[10];
    const float* rpw    = (const float*)d_in[11];
    const float* ln2_w  = (const float*)d_in[12];
    const float* ln2_b  = (const float*)d_in[13];
    const float* fc1_w  = (const float*)d_in[14];
    const float* fc1_b  = (const float*)d_in[15];
    const float* fc2_w  = (const float*)d_in[16];
    const float* fc2_b  = (const float*)d_in[17];

    float *h, *relh, *relw;
    hf *S, *colH, *colL, *xnH, *xnL, *q, *k, *v, *attnH, *attnL, *mlpH, *mlpL;
    hf *cwTH, *cwTL, *qkvTH, *projTH, *projTL, *fc1TH, *fc2TH;
    cudaGetSymbolAddress((void**)&h, g_h);
    cudaGetSymbolAddress((void**)&relh, g_relh);
    cudaGetSymbolAddress((void**)&relw, g_relw);
    cudaGetSymbolAddress((void**)&S, g_S);
    cudaGetSymbolAddress((void**)&colH, g_colH);   cudaGetSymbolAddress((void**)&colL, g_colL);
    cudaGetSymbolAddress((void**)&xnH, g_xnH);     cudaGetSymbolAddress((void**)&xnL, g_xnL);
    cudaGetSymbolAddress((void**)&q, g_q);
    cudaGetSymbolAddress((void**)&k, g_k);
    cudaGetSymbolAddress((void**)&v, g_v);
    cudaGetSymbolAddress((void**)&attnH, g_attnH); cudaGetSymbolAddress((void**)&attnL, g_attnL);
    cudaGetSymbolAddress((void**)&mlpH, g_mlpH);   cudaGetSymbolAddress((void**)&mlpL, g_mlpL);
    cudaGetSymbolAddress((void**)&cwTH, g_cwTH);   cudaGetSymbolAddress((void**)&cwTL, g_cwTL);
    cudaGetSymbolAddress((void**)&qkvTH, g_qkvTH);
    cudaGetSymbolAddress((void**)&projTH, g_projTH); cudaGetSymbolAddress((void**)&projTL, g_projTL);
    cudaGetSymbolAddress((void**)&fc1TH, g_fc1TH);
    cudaGetSymbolAddress((void**)&fc2TH, g_fc2TH);

    constexpr int SM_33 = wg_smem_bytes(128, 128, 32, false, 2, 2);  // 81920  (conv, proj)
    constexpr int SM_21 = wg_smem_bytes(128, 128, 32, false, 2, 1);  // 69632  (qkv, fc1, fc2)
    constexpr int SM_11 = wg_smem_bytes(128, 128, 32, false, 1, 1);  // 69632  (S)
    constexpr int SM_AV = wg_smem_bytes(128, 64, 32, true, 1, 1);    // 36864  (AV)

    cudaFuncSetAttribute((const void*)wgemm<128,128,32,32,64,EPI_CONVPOS,false,2,2>,
                         cudaFuncAttributeMaxDynamicSharedMemorySize, SM_33);
    cudaFuncSetAttribute((const void*)wgemm<128,128,32,32,64,EPI_QKV,false,2,1>,
                         cudaFuncAttributeMaxDynamicSharedMemorySize, SM_21);
    cudaFuncSetAttribute((const void*)wgemm<128,128,32,32,64,EPI_SREL,false,1,1>,
                         cudaFuncAttributeMaxDynamicSharedMemorySize, SM_11);
    cudaFuncSetAttribute((const void*)wgemm<128,64,32,32,32,EPI_AV,true,1,1>,
                         cudaFuncAttributeMaxDynamicSharedMemorySize, SM_AV);
    cudaFuncSetAttribute((const void*)wgemm<128,128,32,32,64,EPI_BIASRES,false,2,2>,
                         cudaFuncAttributeMaxDynamicSharedMemorySize, SM_33);
    cudaFuncSetAttribute((const void*)wgemm<128,128,32,32,64,EPI_GELU,false,2,1>,
                         cudaFuncAttributeMaxDynamicSharedMemorySize, SM_21);
    cudaFuncSetAttribute((const void*)wgemm<128,128,32,32,64,EPI_BIASRES,false,2,1>,
                         cudaFuncAttributeMaxDynamicSharedMemorySize, SM_21);

    const float scale = 0.125f;  // HD^-0.5
    const dim3 tb(32, 8);

    // ---- weight prep ----
    {
        Jobs8 J{};
        for (int l = 0; l < 4; l++) {
            J.j[l]     = { qkv_w  + (size_t)l * EMB * 3 * EMB,
                           qkvTH  + (size_t)l * 3 * EMB * EMB, nullptr, EMB, 3 * EMB, 1 };
            J.j[4 + l] = { proj_w + (size_t)l * EMB * EMB,
                           projTH + (size_t)l * EMB * EMB,
                           projTL + (size_t)l * EMB * EMB, EMB, EMB, 1 };
        }
        prep_kernel<<<dim3(3 * EMB / 32, EMB / 32, 8), tb>>>(J);
    }
    {
        Jobs8 J{};
        for (int l = 0; l < 4; l++)
            J.j[l] = { fc1_w + (size_t)l * EMB * MLPD,
                       fc1TH + (size_t)l * MLPD * EMB, nullptr, EMB, MLPD, 1 };
        prep_kernel<<<dim3(MLPD / 32, EMB / 32, 4), tb>>>(J);
    }
    {
        Jobs8 J{};
        for (int l = 0; l < 4; l++)
            J.j[l] = { fc2_w + (size_t)l * MLPD * EMB,
                       fc2TH + (size_t)l * EMB * MLPD, nullptr, MLPD, EMB, 1 };
        prep_kernel<<<dim3(EMB / 32, MLPD / 32, 4), tb>>>(J);
    }
    {
        Jobs8 J{};
        J.j[0] = { conv_w, cwTH, cwTL, EMB, EMB, 0 };
        prep_kernel<<<dim3(EMB / 32, EMB / 32, 1), tb>>>(J);
    }

    im2col_kernel<<<(TOKENS * EMB + 255) / 256, 256>>>(x, colH, colL);

    // patch embed (3-MMA)
    wgemm<128,128,32,32,64,EPI_CONVPOS,false,2,2><<<dim3(EMB/128, TOKENS/128), 256, SM_33>>>(
        colH, colL, EMB, cwTH, cwTL, EMB, h, EMB, EMB, 0, 0, 0,
        conv_b, pos, nullptr, nullptr, nullptr, nullptr, nullptr, 0.f);

    for (int i = 0; i < 4; i++) {
        ln_kernel<<<TOKENS, 256>>>(h, ln1_w + i * EMB, ln1_b + i * EMB, xnH, xnL);

        // QKV: activation split x fp16 weights (2-MMA); writes single-plane q/k/v
        wgemm<128,128,32,32,64,EPI_QKV,false,2,1><<<dim3(3*EMB/128, TOKENS/128), 256, SM_21>>>(
            xnH, xnL, EMB,
            qkvTH + (size_t)i * 3 * EMB * EMB, nullptr, EMB,
            nullptr, 3 * EMB, EMB, 0, 0, 0,
            qkv_b + (size_t)i * 3 * EMB, nullptr, nullptr,
            q, nullptr, k, v, 0.f);

        rel_kernel<<<BHEADS * SEQ, 64>>>(q, rph + (size_t)i * 63 * HD, rpw + (size_t)i * 63 * HD,
                                         relh, relw);

        // S = scale*q@k^T + rel (1-MMA, fp16 logits out)
        wgemm<128,128,32,32,64,EPI_SREL,false,1,1><<<dim3(SEQ/128, SEQ/128, BHEADS), 256, SM_11>>>(
            q, nullptr, HD, k, nullptr, HD, nullptr, SEQ, HD,
            (size_t)SEQ * HD, (size_t)SEQ * HD, (size_t)SEQ * SEQ,
            nullptr, relh, relw,
            S, nullptr, nullptr, nullptr, scale);

        softmax_kernel<<<BHEADS * SEQ, 256>>>(S);

        // O = P @ v (1-MMA); split-store attn planes
        wgemm<128,64,32,32,32,EPI_AV,true,1,1><<<dim3(1, SEQ/128, BHEADS), 256, SM_AV>>>(
            S, nullptr, SEQ, v, nullptr, HD,
            nullptr, HD, SEQ,
            (size_t)SEQ * SEQ, (size_t)SEQ * HD, 0,
            nullptr, nullptr, nullptr,
            attnH, attnL, nullptr, nullptr, 0.f);

        // proj (3-MMA) + residual
        wgemm<128,128,32,32,64,EPI_BIASRES,false,2,2><<<dim3(EMB/128, TOKENS/128), 256, SM_33>>>(
            attnH, attnL, EMB,
            projTH + (size_t)i * EMB * EMB, projTL + (size_t)i * EMB * EMB, EMB,
            h, EMB, EMB, 0, 0, 0,
            proj_b + (size_t)i * EMB, h, nullptr,
            nullptr, nullptr, nullptr, nullptr, 0.f);

        ln_kernel<<<TOKENS, 256>>>(h, ln2_w + i * EMB, ln2_b + i * EMB, xnH, xnL);

        // fc1 (2-MMA) + GELU
        wgemm<128,128,32,32,64,EPI_GELU,false,2,1><<<dim3(MLPD/128, TOKENS/128), 256, SM_21>>>(
            xnH, xnL, EMB,
            fc1TH + (size_t)i * MLPD * EMB, nullptr, EMB,
            nullptr, MLPD, EMB, 0, 0, 0,
            fc1_b + (size_t)i * MLPD, nullptr, nullptr,
            mlpH, mlpL, nullptr, nullptr, 0.f);

        // fc2 (2-MMA) + residual
        float* dst = (i == 3) ? (float*)d_out : h;
        wgemm<128,128,32,32,64,EPI_BIASRES,false,2,1><<<dim3(EMB/128, TOKENS/128), 256, SM_21>>>(
            mlpH, mlpL, MLPD,
            fc2TH + (size_t)i * EMB * MLPD, nullptr, MLPD,
            dst, EMB, MLPD, 0, 0, 0,
            fc2_b + (size_t)i * EMB, h, nullptr,
            nullptr, nullptr, nullptr, nullptr, 0.f);
    }
}